// round 6
// baseline (speedup 1.0000x reference)
#include <cuda_runtime.h>
#include <math.h>

#define BSZ 4096
#define HD  128
#define TDIM 768

// ---------------- device scratch ----------------
__device__ float g_LN[BSZ * HD];        // normalized logits  [B][128]
__device__ float g_Tn[BSZ];             // teacher row inv-norms
__device__ float g_Ht[HD * BSZ];        // hash^T   [128][4096]
__device__ float g_Tt[TDIM * BSZ];      // normalized teacher^T [768][4096]
__device__ float g_GH[HD * HD];         // H^T H
__device__ float g_C [HD * TDIM];       // H^T T
__device__ float g_TT[TDIM * TDIM];     // T^T T
__device__ float g_denom[BSZ];
__device__ float g_pos[BSZ];
__device__ float g_cnt[BSZ];
__device__ float g_quant;
__device__ float g_ST;

__device__ __forceinline__ void mma_tf32(float* d, const unsigned* a, const unsigned* b) {
    asm volatile(
        "mma.sync.aligned.m16n8k8.row.col.f32.tf32.tf32.f32 "
        "{%0,%1,%2,%3}, {%4,%5,%6,%7}, {%8,%9}, {%0,%1,%2,%3};"
        : "+f"(d[0]), "+f"(d[1]), "+f"(d[2]), "+f"(d[3])
        : "r"(a[0]), "r"(a[1]), "r"(a[2]), "r"(a[3]), "r"(b[0]), "r"(b[1]));
}

// ---------------- zero accumulators ----------------
__global__ void k_zero() {
    int i = blockIdx.x * 256 + threadIdx.x;
    int n = gridDim.x * 256;
    for (int j = i; j < TDIM * TDIM; j += n) g_TT[j] = 0.f;
    for (int j = i; j < HD * TDIM;  j += n) g_C[j]  = 0.f;
    if (i < HD * HD) g_GH[i] = 0.f;
    if (i < BSZ) g_denom[i] = 0.f;
    if (i == 0) { g_quant = 0.f; g_ST = 0.f; }
}

// ---------------- normalize logits + quant partial ----------------
__global__ void k_norm_logits(const float* __restrict__ x) {
    int row = blockIdx.x;
    int t = threadIdx.x;                 // 128 threads
    float v = x[row * HD + t];
    float ss = v * v;
    float q = fabsf(fabsf(v) - 1.0f);
    #pragma unroll
    for (int o = 16; o >= 1; o >>= 1) {
        ss += __shfl_xor_sync(0xffffffffu, ss, o);
        q  += __shfl_xor_sync(0xffffffffu, q, o);
    }
    __shared__ float sred[4], qred[4];
    __shared__ float sinv;
    int w = t >> 5, l = t & 31;
    if (l == 0) { sred[w] = ss; qred[w] = q; }
    __syncthreads();
    if (t == 0) {
        float tot = sred[0] + sred[1] + sred[2] + sred[3];
        float qt  = qred[0] + qred[1] + qred[2] + qred[3];
        atomicAdd(&g_quant, qt);
        sinv = 1.0f / fmaxf(sqrtf(tot), 1e-12f);
    }
    __syncthreads();
    g_LN[row * HD + t] = v * sinv;
}

// ---------------- teacher row inv norms ----------------
__global__ void k_tnorm(const float* __restrict__ x) {
    int row = blockIdx.x;
    int t = threadIdx.x;                 // 256 threads
    float v0 = x[row * TDIM + t];
    float v1 = x[row * TDIM + 256 + t];
    float v2 = x[row * TDIM + 512 + t];
    float ss = v0 * v0 + v1 * v1 + v2 * v2;
    #pragma unroll
    for (int o = 16; o >= 1; o >>= 1) ss += __shfl_xor_sync(0xffffffffu, ss, o);
    __shared__ float sred[8];
    if ((t & 31) == 0) sred[t >> 5] = ss;
    __syncthreads();
    if (t == 0) {
        float tot = 0.f;
        #pragma unroll
        for (int i = 0; i < 8; i++) tot += sred[i];
        g_Tn[row] = 1.0f / fmaxf(sqrtf(tot), 1e-12f);
    }
}

// ---------------- tiled transpose (optional row scaling) ----------------
__global__ void k_transpose(const float* __restrict__ src, float* __restrict__ dst,
                            int R, int C, int scaled) {
    __shared__ float t[32][33];
    int c0 = blockIdx.x * 32, r0 = blockIdx.y * 32;
    int x = threadIdx.x, y = threadIdx.y;   // block (32, 8)
    #pragma unroll
    for (int i = 0; i < 32; i += 8) {
        float v = src[(r0 + y + i) * C + c0 + x];
        if (scaled) v *= g_Tn[r0 + y + i];
        t[y + i][x] = v;
    }
    __syncthreads();
    #pragma unroll
    for (int i = 0; i < 32; i += 8) dst[(c0 + y + i) * R + r0 + x] = t[x][y + i];
}

// ---------------- per-row mask scan + exact positive dots (no atomics) ------
__global__ void __launch_bounds__(128) k_posrow(const int* __restrict__ pmask) {
    __shared__ float ln[HD];
    __shared__ float pred[4], cred[4];
    int row = blockIdx.x;
    int t = threadIdx.x;                 // 128 threads
    ln[t] = g_LN[row * HD + t];
    __syncthreads();
    const int4* m4 = (const int4*)(pmask + row * BSZ);
    const float4* LN4 = (const float4*)g_LN;   // row stride 32 float4
    float ps = 0.f, cs = 0.f;
    #pragma unroll
    for (int s = 0; s < 8; s++) {
        int4 v = m4[t + s * 128];              // coalesced
        int base = (t + s * 128) << 2;
        #pragma unroll
        for (int k = 0; k < 4; k++) {
            int e = (k == 0) ? v.x : (k == 1) ? v.y : (k == 2) ? v.z : v.w;
            if (e != 0) {
                int j = base + k;
                float d = 0.f;
                #pragma unroll
                for (int u = 0; u < 32; u++) {
                    float4 b = LN4[j * 32 + u];
                    d += ln[u * 4] * b.x + ln[u * 4 + 1] * b.y
                       + ln[u * 4 + 2] * b.z + ln[u * 4 + 3] * b.w;
                }
                ps += d; cs += 1.f;
            }
        }
    }
    #pragma unroll
    for (int o = 16; o >= 1; o >>= 1) {
        ps += __shfl_xor_sync(0xffffffffu, ps, o);
        cs += __shfl_xor_sync(0xffffffffu, cs, o);
    }
    int w = t >> 5;
    if ((t & 31) == 0) { pred[w] = ps; cred[w] = cs; }
    __syncthreads();
    if (t == 0) {
        g_pos[row] = (pred[0] + pred[1] + pred[2] + pred[3]) * 5.0f;
        g_cnt[row] = cred[0] + cred[1] + cred[2] + cred[3];
    }
}

// ======== 128x128 mma tile core ========
// smem: unsigned [128][36]; bank = (4r + c) & 31 -> conflict-free frag reads
// 8 warps = 2(wm) x 4(wn); warp tile 64x32; frags 4(mi) x 4(ni)

#define LOAD_TILES(A4src, B4src)                                            \
    do {                                                                    \
        _Pragma("unroll")                                                   \
        for (int s = 0; s < 4; s++) {                                       \
            int idx = tid + s * 256;                                        \
            int r = idx >> 3, c8 = idx & 7;                                 \
            *(float4*)&As[r][c8 * 4] = (A4src);                             \
            *(float4*)&Bs[r][c8 * 4] = (B4src);                             \
        }                                                                   \
    } while (0)

#define MMA_CHUNK()                                                         \
    do {                                                                    \
        _Pragma("unroll")                                                   \
        for (int kk = 0; kk < 4; kk++) {                                    \
            int kb = kk * 8;                                                \
            unsigned af[4][4], bf[4][2];                                    \
            _Pragma("unroll")                                               \
            for (int mi = 0; mi < 4; mi++) {                                \
                int rr = wm * 64 + mi * 16 + fr;                            \
                af[mi][0] = As[rr][kb + fc];                                \
                af[mi][1] = As[rr + 8][kb + fc];                            \
                af[mi][2] = As[rr][kb + fc + 4];                            \
                af[mi][3] = As[rr + 8][kb + fc + 4];                        \
            }                                                               \
            _Pragma("unroll")                                               \
            for (int ni = 0; ni < 4; ni++) {                                \
                int rn = wn * 32 + ni * 8 + fr;                             \
                bf[ni][0] = Bs[rn][kb + fc];                                \
                bf[ni][1] = Bs[rn][kb + fc + 4];                            \
            }                                                               \
            _Pragma("unroll")                                               \
            for (int mi = 0; mi < 4; mi++)                                  \
                _Pragma("unroll")                                           \
                for (int ni = 0; ni < 4; ni++)                              \
                    mma_tf32(acc[mi][ni], af[mi], bf[ni]);                  \
        }                                                                   \
    } while (0)

// ---------------- generic A*B^T GEMM (k-contig operands), split-K ----------
__global__ void __launch_bounds__(256) k_mma(const float* __restrict__ A,
                                             const float* __restrict__ Bm,
                                             float* __restrict__ out, int ldo,
                                             int kPer) {
    __shared__ __align__(16) unsigned As[128][36];
    __shared__ __align__(16) unsigned Bs[128][36];
    int m0 = blockIdx.x * 128, n0 = blockIdx.y * 128;
    int kBeg = blockIdx.z * kPer;
    int tid = threadIdx.x, lane = tid & 31, w = tid >> 5;
    int wm = w & 1, wn = w >> 1;
    int fr = lane >> 2, fc = lane & 3;
    const float4* A4 = (const float4*)A;    // row stride 1024 float4
    const float4* B4 = (const float4*)Bm;
    float acc[4][4][4] = {};
    for (int k0 = kBeg; k0 < kBeg + kPer; k0 += 32) {
        __syncthreads();
        LOAD_TILES(A4[(m0 + r) * 1024 + (k0 >> 2) + c8],
                   B4[(n0 + r) * 1024 + (k0 >> 2) + c8]);
        __syncthreads();
        MMA_CHUNK();
    }
    #pragma unroll
    for (int mi = 0; mi < 4; mi++)
        #pragma unroll
        for (int ni = 0; ni < 4; ni++)
            #pragma unroll
            for (int h = 0; h < 2; h++)
                #pragma unroll
                for (int q = 0; q < 2; q++) {
                    int gi = m0 + wm * 64 + mi * 16 + fr + h * 8;
                    int gj = n0 + wn * 32 + ni * 8 + fc * 2 + q;
                    atomicAdd(&out[gi * ldo + gj], acc[mi][ni][h * 2 + q]);
                }
}

// ---------------- T^T T upper-triangle 128-tiles ----------------
__global__ void __launch_bounds__(256) k_mma_tri(int kPer) {
    __shared__ __align__(16) unsigned As[128][36];
    __shared__ __align__(16) unsigned Bs[128][36];
    int t = blockIdx.x, tm = 0;                 // 6x6 tiles, upper = 21
    while (t >= 6 - tm) { t -= 6 - tm; tm++; }
    int m0 = tm * 128, n0 = (tm + t) * 128;
    int kBeg = blockIdx.z * kPer;
    int tid = threadIdx.x, lane = tid & 31, w = tid >> 5;
    int wm = w & 1, wn = w >> 1;
    int fr = lane >> 2, fc = lane & 3;
    const float4* A4 = (const float4*)g_Tt;
    float acc[4][4][4] = {};
    for (int k0 = kBeg; k0 < kBeg + kPer; k0 += 32) {
        __syncthreads();
        LOAD_TILES(A4[(m0 + r) * 1024 + (k0 >> 2) + c8],
                   A4[(n0 + r) * 1024 + (k0 >> 2) + c8]);
        __syncthreads();
        MMA_CHUNK();
    }
    #pragma unroll
    for (int mi = 0; mi < 4; mi++)
        #pragma unroll
        for (int ni = 0; ni < 4; ni++)
            #pragma unroll
            for (int h = 0; h < 2; h++)
                #pragma unroll
                for (int q = 0; q < 2; q++) {
                    int gi = m0 + wm * 64 + mi * 16 + fr + h * 8;
                    int gj = n0 + wn * 32 + ni * 8 + fc * 2 + q;
                    atomicAdd(&g_TT[gi * TDIM + gj], acc[mi][ni][h * 2 + q]);
                }
}

// ---------------- distill square-reduce ----------------
__global__ void k_sq3() {
    int i = blockIdx.x * 256 + threadIdx.x;
    int n = gridDim.x * 256;
    float s = 0.f;
    for (int j = i; j < HD * HD; j += n) {
        float v = g_GH[j]; s += v * v * (1.f / (128.f * 128.f));
    }
    for (int j = i; j < HD * TDIM; j += n) {
        float v = g_C[j]; s -= 2.f * v * v * (1.f / 128.f);
    }
    for (int j = i; j < TDIM * TDIM; j += n) {
        int r = j / TDIM, c = j % TDIM;
        if (c < r) continue;
        float v = g_TT[j];
        s += (c == r) ? v * v : 2.f * v * v;
    }
    #pragma unroll
    for (int o = 16; o >= 1; o >>= 1) s += __shfl_xor_sync(0xffffffffu, s, o);
    __shared__ float red[8];
    if ((threadIdx.x & 31) == 0) red[threadIdx.x >> 5] = s;
    __syncthreads();
    if (threadIdx.x == 0) {
        float tot = 0.f;
        #pragma unroll
        for (int k = 0; k < 8; k++) tot += red[k];
        atomicAdd(&g_ST, tot / ((float)BSZ * (float)BSZ));
    }
}

// ---------------- contrastive: symmetric upper-tri 128-tiles, denom only ----
__global__ void __launch_bounds__(256) k_cont() {
    __shared__ __align__(16) unsigned As[128][36];
    __shared__ __align__(16) unsigned Bs[128][36];
    __shared__ float sRd[128], sCd[128];
    int t = blockIdx.x, tm = 0;                 // 32x32 tiles, upper = 528
    while (t >= 32 - tm) { t -= 32 - tm; tm++; }
    int i0 = tm * 128, j0 = (tm + t) * 128;
    bool diag = (i0 == j0);
    int tid = threadIdx.x, lane = tid & 31, w = tid >> 5;
    int wm = w & 1, wn = w >> 1;
    int fr = lane >> 2, fc = lane & 3;
    if (tid < 128) { sRd[tid] = 0.f; sCd[tid] = 0.f; }
    const float4* LN4 = (const float4*)g_LN;   // row stride = 32 float4
    float acc[4][4][4] = {};
    #pragma unroll
    for (int kc = 0; kc < 4; kc++) {
        __syncthreads();
        LOAD_TILES(LN4[(i0 + r) * 32 + kc * 8 + c8],
                   LN4[(j0 + r) * 32 + kc * 8 + c8]);
        __syncthreads();
        MMA_CHUNK();
    }

    // ---- epilogue: exp sums, both orientations ----
    float dR[4][2] = {}, dC[4][2] = {};
    #pragma unroll
    for (int mi = 0; mi < 4; mi++)
        #pragma unroll
        for (int ni = 0; ni < 4; ni++)
            #pragma unroll
            for (int h = 0; h < 2; h++)
                #pragma unroll
                for (int q = 0; q < 2; q++) {
                    int gi = i0 + wm * 64 + mi * 16 + fr + h * 8;
                    int gj = j0 + wn * 32 + ni * 8 + fc * 2 + q;
                    float e = __expf(acc[mi][ni][h * 2 + q] * 5.0f);
                    if (gj != gi) dR[mi][h] += e;
                    if (!diag) dC[ni][q] += e;
                }
    // row reduce over fc lanes (width 4)
    #pragma unroll
    for (int mi = 0; mi < 4; mi++)
        #pragma unroll
        for (int h = 0; h < 2; h++) {
            #pragma unroll
            for (int o = 2; o >= 1; o >>= 1)
                dR[mi][h] += __shfl_down_sync(0xffffffffu, dR[mi][h], o, 4);
            if (fc == 0)
                atomicAdd(&sRd[wm * 64 + mi * 16 + fr + h * 8], dR[mi][h]);
        }
    // col reduce over fr lanes (xor 4,8,16)
    if (!diag) {
        #pragma unroll
        for (int ni = 0; ni < 4; ni++)
            #pragma unroll
            for (int q = 0; q < 2; q++) {
                #pragma unroll
                for (int o = 16; o >= 4; o >>= 1)
                    dC[ni][q] += __shfl_xor_sync(0xffffffffu, dC[ni][q], o);
                if (fr == 0)
                    atomicAdd(&sCd[wn * 32 + ni * 8 + fc * 2 + q], dC[ni][q]);
            }
    }
    __syncthreads();
    if (tid < 128) {
        atomicAdd(&g_denom[i0 + tid], sRd[tid]);
        if (!diag) atomicAdd(&g_denom[j0 + tid], sCd[tid]);
    }
}

// ---------------- final combine ----------------
__global__ void k_combine(float* __restrict__ out) {
    int tid = threadIdx.x;               // 256 threads
    float cont = 0.f;
    for (int i = tid; i < BSZ; i += 256)
        cont += logf(g_denom[i]) - g_pos[i] / fmaxf(g_cnt[i], 1.0f);
    #pragma unroll
    for (int o = 16; o >= 1; o >>= 1)
        cont += __shfl_xor_sync(0xffffffffu, cont, o);
    __shared__ float r0[8];
    if ((tid & 31) == 0) r0[tid >> 5] = cont;
    __syncthreads();
    if (tid == 0) {
        float cT = 0.f;
        #pragma unroll
        for (int i = 0; i < 8; i++) cT += r0[i];
        float quant = g_quant / ((float)BSZ * (float)HD);
        out[0] = cT / (float)BSZ + 0.5f * g_ST + 0.01f * quant;
    }
}

// ---------------- launch ----------------
extern "C" void kernel_launch(void* const* d_in, const int* in_sizes, int n_in,
                              void* d_out, int out_size) {
    const float* logits = (const float*)d_in[0];
    const float* hash   = (const float*)d_in[1];
    const float* teach  = (const float*)d_in[2];
    const int*   pmask  = (const int*)d_in[3];
    float* out = (float*)d_out;

    float* p_Ht; cudaGetSymbolAddress((void**)&p_Ht, g_Ht);
    float* p_Tt; cudaGetSymbolAddress((void**)&p_Tt, g_Tt);
    float* p_GH; cudaGetSymbolAddress((void**)&p_GH, g_GH);
    float* p_C;  cudaGetSymbolAddress((void**)&p_C,  g_C);

    k_zero<<<512, 256>>>();
    k_norm_logits<<<BSZ, 128>>>(logits);
    k_tnorm<<<BSZ, 256>>>(teach);
    k_transpose<<<dim3(HD / 32, BSZ / 32), dim3(32, 8)>>>(hash, p_Ht, BSZ, HD, 0);
    k_transpose<<<dim3(TDIM / 32, BSZ / 32), dim3(32, 8)>>>(teach, p_Tt, BSZ, TDIM, 1);
    k_posrow<<<BSZ, 128>>>(pmask);
    // G_H = H^T H : one 128-tile, split-K 32
    k_mma<<<dim3(1, 1, 32), 256>>>(p_Ht, p_Ht, p_GH, HD, 128);
    // C = H^T T : 1x6 tiles, split-K 16
    k_mma<<<dim3(1, 6, 16), 256>>>(p_Ht, p_Tt, p_C, TDIM, 256);
    // T^T T upper triangle : 21 tiles, split-K 16
    k_mma_tri<<<dim3(21, 1, 16), 256>>>(256);
    k_sq3<<<512, 256>>>();
    // contrastive: 528 upper-triangle 128-tiles
    k_cont<<<528, 256>>>();
    k_combine<<<1, 256>>>(out);
}

// round 7
// speedup vs baseline: 1.6188x; 1.6188x over previous
#include <cuda_runtime.h>
#include <math.h>

#define BSZ 4096
#define HD  128
#define TDIM 768

// ---------------- device scratch ----------------
__device__ float g_LN[BSZ * HD];        // normalized logits  [B][128]
__device__ float g_Tn[BSZ];             // teacher row inv-norms
__device__ float g_Ht[HD * BSZ];        // hash^T   [128][4096]
__device__ float g_Tt[TDIM * BSZ];      // normalized teacher^T [768][4096]
__device__ float g_GH[HD * HD];         // H^T H
__device__ float g_C [HD * TDIM];       // H^T T
__device__ float g_TT[TDIM * TDIM];     // T^T T (upper triangle valid)
__device__ float g_denom[BSZ];
__device__ float g_pos[BSZ];
__device__ float g_cnt[BSZ];
__device__ float g_quant;
__device__ float g_ST;

__device__ __forceinline__ void mma_tf32(float* d, const unsigned* a, const unsigned* b) {
    asm volatile(
        "mma.sync.aligned.m16n8k8.row.col.f32.tf32.tf32.f32 "
        "{%0,%1,%2,%3}, {%4,%5,%6,%7}, {%8,%9}, {%0,%1,%2,%3};"
        : "+f"(d[0]), "+f"(d[1]), "+f"(d[2]), "+f"(d[3])
        : "r"(a[0]), "r"(a[1]), "r"(a[2]), "r"(a[3]), "r"(b[0]), "r"(b[1]));
}

// ---------------- zero accumulators ----------------
__global__ void k_zero() {
    int i = blockIdx.x * 256 + threadIdx.x;
    int n = gridDim.x * 256;
    for (int j = i; j < TDIM * TDIM; j += n) g_TT[j] = 0.f;
    for (int j = i; j < HD * TDIM;  j += n) g_C[j]  = 0.f;
    if (i < HD * HD) g_GH[i] = 0.f;
    if (i < BSZ) { g_denom[i] = 0.f; g_pos[i] = 0.f; g_cnt[i] = 0.f; }
    if (i == 0) { g_quant = 0.f; g_ST = 0.f; }
}

// ---------------- normalize logits + quant partial ----------------
__global__ void k_norm_logits(const float* __restrict__ x) {
    int row = blockIdx.x;
    int t = threadIdx.x;                 // 128 threads
    float v = x[row * HD + t];
    float ss = v * v;
    float q = fabsf(fabsf(v) - 1.0f);
    #pragma unroll
    for (int o = 16; o >= 1; o >>= 1) {
        ss += __shfl_xor_sync(0xffffffffu, ss, o);
        q  += __shfl_xor_sync(0xffffffffu, q, o);
    }
    __shared__ float sred[4], qred[4];
    __shared__ float sinv;
    int w = t >> 5, l = t & 31;
    if (l == 0) { sred[w] = ss; qred[w] = q; }
    __syncthreads();
    if (t == 0) {
        float tot = sred[0] + sred[1] + sred[2] + sred[3];
        float qt  = qred[0] + qred[1] + qred[2] + qred[3];
        atomicAdd(&g_quant, qt);
        sinv = 1.0f / fmaxf(sqrtf(tot), 1e-12f);
    }
    __syncthreads();
    g_LN[row * HD + t] = v * sinv;
}

// ---------------- teacher row inv norms ----------------
__global__ void k_tnorm(const float* __restrict__ x) {
    int row = blockIdx.x;
    int t = threadIdx.x;                 // 256 threads
    float v0 = x[row * TDIM + t];
    float v1 = x[row * TDIM + 256 + t];
    float v2 = x[row * TDIM + 512 + t];
    float ss = v0 * v0 + v1 * v1 + v2 * v2;
    #pragma unroll
    for (int o = 16; o >= 1; o >>= 1) ss += __shfl_xor_sync(0xffffffffu, ss, o);
    __shared__ float sred[8];
    if ((t & 31) == 0) sred[t >> 5] = ss;
    __syncthreads();
    if (t == 0) {
        float tot = 0.f;
        #pragma unroll
        for (int i = 0; i < 8; i++) tot += sred[i];
        g_Tn[row] = 1.0f / fmaxf(sqrtf(tot), 1e-12f);
    }
}

// ---------------- tiled transpose (optional row scaling) ----------------
__global__ void k_transpose(const float* __restrict__ src, float* __restrict__ dst,
                            int R, int C, int scaled) {
    __shared__ float t[32][33];
    int c0 = blockIdx.x * 32, r0 = blockIdx.y * 32;
    int x = threadIdx.x, y = threadIdx.y;   // block (32, 8)
    #pragma unroll
    for (int i = 0; i < 32; i += 8) {
        float v = src[(r0 + y + i) * C + c0 + x];
        if (scaled) v *= g_Tn[r0 + y + i];
        t[y + i][x] = v;
    }
    __syncthreads();
    #pragma unroll
    for (int i = 0; i < 32; i += 8) dst[(c0 + y + i) * R + r0 + x] = t[x][y + i];
}

// ======== 64x64 double-buffered mma tile core, K-chunk 32 ========
// smem: unsigned [2][64][36]; 36 mod 32 = 4 -> frag bank = (4fr+fc), conflict-free
// 8 warps = 2(wm) x 4(wn); warp tile 32x16; frags 2(mi) x 2(ni)

#define LDG_TILES(A4expr, B4expr)                                           \
    do {                                                                    \
        _Pragma("unroll")                                                   \
        for (int s = 0; s < 2; s++) {                                       \
            int idx = tid + s * 256;                                        \
            int r = idx >> 3, c8 = idx & 7;                                 \
            ra[s] = (A4expr);                                               \
            rb[s] = (B4expr);                                               \
        }                                                                   \
    } while (0)

#define STS_TILES(st)                                                       \
    do {                                                                    \
        _Pragma("unroll")                                                   \
        for (int s = 0; s < 2; s++) {                                       \
            int idx = tid + s * 256;                                        \
            int r = idx >> 3, c8 = idx & 7;                                 \
            *(float4*)&As[st][r][c8 * 4] = ra[s];                           \
            *(float4*)&Bs[st][r][c8 * 4] = rb[s];                           \
        }                                                                   \
    } while (0)

#define MMA_CHUNK(st)                                                       \
    do {                                                                    \
        _Pragma("unroll")                                                   \
        for (int kk = 0; kk < 4; kk++) {                                    \
            int kb = kk * 8;                                                \
            unsigned af[2][4], bf[2][2];                                    \
            _Pragma("unroll")                                               \
            for (int mi = 0; mi < 2; mi++) {                                \
                int rr = wm * 32 + mi * 16 + fr;                            \
                af[mi][0] = As[st][rr][kb + fc];                            \
                af[mi][1] = As[st][rr + 8][kb + fc];                        \
                af[mi][2] = As[st][rr][kb + fc + 4];                        \
                af[mi][3] = As[st][rr + 8][kb + fc + 4];                    \
            }                                                               \
            _Pragma("unroll")                                               \
            for (int ni = 0; ni < 2; ni++) {                                \
                int rn = wn * 16 + ni * 8 + fr;                             \
                bf[ni][0] = Bs[st][rn][kb + fc];                            \
                bf[ni][1] = Bs[st][rn][kb + fc + 4];                        \
            }                                                               \
            _Pragma("unroll")                                               \
            for (int mi = 0; mi < 2; mi++)                                  \
                _Pragma("unroll")                                           \
                for (int ni = 0; ni < 2; ni++)                              \
                    mma_tf32(acc[mi][ni], af[mi], bf[ni]);                  \
        }                                                                   \
    } while (0)

// ---------------- generic A*B^T GEMM (k-contig operands), split-K ----------
__global__ void __launch_bounds__(256) k_gemm(const float* __restrict__ A,
                                              const float* __restrict__ Bm,
                                              float* __restrict__ out, int ldo,
                                              int kPer) {
    __shared__ __align__(16) unsigned As[2][64][36];
    __shared__ __align__(16) unsigned Bs[2][64][36];
    int m0 = blockIdx.x * 64, n0 = blockIdx.y * 64;
    int kBeg = blockIdx.z * kPer;
    int tid = threadIdx.x, lane = tid & 31, w = tid >> 5;
    int wm = w & 1, wn = w >> 1;
    int fr = lane >> 2, fc = lane & 3;
    const float4* A4 = (const float4*)A;    // row stride 1024 float4
    const float4* B4 = (const float4*)Bm;
    float acc[2][2][4] = {};
    float4 ra[2], rb[2];
    int nCh = kPer >> 5;
    int kcur = kBeg;
    LDG_TILES(A4[(m0 + r) * 1024 + (kcur >> 2) + c8],
              B4[(n0 + r) * 1024 + (kcur >> 2) + c8]);
    STS_TILES(0);
    __syncthreads();
    for (int c = 0; c < nCh; c++) {
        int st = c & 1;
        if (c + 1 < nCh) {
            kcur = kBeg + (c + 1) * 32;
            LDG_TILES(A4[(m0 + r) * 1024 + (kcur >> 2) + c8],
                      B4[(n0 + r) * 1024 + (kcur >> 2) + c8]);
        }
        MMA_CHUNK(st);
        if (c + 1 < nCh) STS_TILES(1 - st);
        __syncthreads();
    }
    #pragma unroll
    for (int mi = 0; mi < 2; mi++)
        #pragma unroll
        for (int ni = 0; ni < 2; ni++)
            #pragma unroll
            for (int h = 0; h < 2; h++)
                #pragma unroll
                for (int q = 0; q < 2; q++) {
                    int gi = m0 + wm * 32 + mi * 16 + fr + h * 8;
                    int gj = n0 + wn * 16 + ni * 8 + fc * 2 + q;
                    atomicAdd(&out[gi * ldo + gj], acc[mi][ni][h * 2 + q]);
                }
}

// ---------------- T^T T upper-triangle tiles ----------------
__global__ void __launch_bounds__(256) k_gemm_tri(int kPer) {
    __shared__ __align__(16) unsigned As[2][64][36];
    __shared__ __align__(16) unsigned Bs[2][64][36];
    int t = blockIdx.x, tm = 0;                 // 12x12 tiles, upper = 78
    while (t >= 12 - tm) { t -= 12 - tm; tm++; }
    int m0 = tm * 64, n0 = (tm + t) * 64;
    int kBeg = blockIdx.z * kPer;
    int tid = threadIdx.x, lane = tid & 31, w = tid >> 5;
    int wm = w & 1, wn = w >> 1;
    int fr = lane >> 2, fc = lane & 3;
    const float4* A4 = (const float4*)g_Tt;
    float acc[2][2][4] = {};
    float4 ra[2], rb[2];
    int nCh = kPer >> 5;
    int kcur = kBeg;
    LDG_TILES(A4[(m0 + r) * 1024 + (kcur >> 2) + c8],
              A4[(n0 + r) * 1024 + (kcur >> 2) + c8]);
    STS_TILES(0);
    __syncthreads();
    for (int c = 0; c < nCh; c++) {
        int st = c & 1;
        if (c + 1 < nCh) {
            kcur = kBeg + (c + 1) * 32;
            LDG_TILES(A4[(m0 + r) * 1024 + (kcur >> 2) + c8],
                      A4[(n0 + r) * 1024 + (kcur >> 2) + c8]);
        }
        MMA_CHUNK(st);
        if (c + 1 < nCh) STS_TILES(1 - st);
        __syncthreads();
    }
    #pragma unroll
    for (int mi = 0; mi < 2; mi++)
        #pragma unroll
        for (int ni = 0; ni < 2; ni++)
            #pragma unroll
            for (int h = 0; h < 2; h++)
                #pragma unroll
                for (int q = 0; q < 2; q++) {
                    int gi = m0 + wm * 32 + mi * 16 + fr + h * 8;
                    int gj = n0 + wn * 16 + ni * 8 + fc * 2 + q;
                    atomicAdd(&g_TT[gi * TDIM + gj], acc[mi][ni][h * 2 + q]);
                }
}

// ---------------- distill square-reduce ----------------
__global__ void k_sq3() {
    int i = blockIdx.x * 256 + threadIdx.x;
    int n = gridDim.x * 256;
    float s = 0.f;
    for (int j = i; j < HD * HD; j += n) {
        float v = g_GH[j]; s += v * v * (1.f / (128.f * 128.f));
    }
    for (int j = i; j < HD * TDIM; j += n) {
        float v = g_C[j]; s -= 2.f * v * v * (1.f / 128.f);
    }
    for (int j = i; j < TDIM * TDIM; j += n) {
        int r = j / TDIM, c = j % TDIM;
        if (c < r) continue;
        float v = g_TT[j];
        s += (c == r) ? v * v : 2.f * v * v;
    }
    #pragma unroll
    for (int o = 16; o >= 1; o >>= 1) s += __shfl_xor_sync(0xffffffffu, s, o);
    __shared__ float red[8];
    if ((threadIdx.x & 31) == 0) red[threadIdx.x >> 5] = s;
    __syncthreads();
    if (threadIdx.x == 0) {
        float tot = 0.f;
        #pragma unroll
        for (int k = 0; k < 8; k++) tot += red[k];
        atomicAdd(&g_ST, tot / ((float)BSZ * (float)BSZ));
    }
}

// ---------------- contrastive: symmetric upper-triangle tiles ----------------
__global__ void __launch_bounds__(256) k_cont(const int* __restrict__ pmask) {
    __shared__ __align__(16) unsigned As[2][64][36];
    __shared__ __align__(16) unsigned Bs[2][64][36];
    __shared__ float sCd[64], sCp[64], sCc[64];
    int t = blockIdx.x, tm = 0;                 // 64x64 tiles, upper = 2080
    while (t >= 64 - tm) { t -= 64 - tm; tm++; }
    int i0 = tm * 64, j0 = (tm + t) * 64;
    bool diag = (i0 == j0);
    int tid = threadIdx.x, lane = tid & 31, w = tid >> 5;
    int wm = w & 1, wn = w >> 1;
    int fr = lane >> 2, fc = lane & 3;
    if (tid < 64) { sCd[tid] = 0.f; sCp[tid] = 0.f; sCc[tid] = 0.f; }
    const float4* LN4 = (const float4*)g_LN;   // row stride = 32 float4
    float acc[2][2][4] = {};
    float4 ra[2], rb[2];
    LDG_TILES(LN4[(i0 + r) * 32 + c8], LN4[(j0 + r) * 32 + c8]);
    STS_TILES(0);
    __syncthreads();
    #pragma unroll
    for (int c = 0; c < 4; c++) {
        int st = c & 1;
        if (c + 1 < 4) {
            LDG_TILES(LN4[(i0 + r) * 32 + (c + 1) * 8 + c8],
                      LN4[(j0 + r) * 32 + (c + 1) * 8 + c8]);
        }
        MMA_CHUNK(st);
        if (c + 1 < 4) STS_TILES(1 - st);
        __syncthreads();
    }

    // ---- epilogue: exp/denom + masked pos (both orientations) ----
    float dR[2][2] = {}, pR[2][2] = {}, cR[2][2] = {};
    float dC[2][2] = {}, pC[2][2] = {}, cC[2][2] = {};
    #pragma unroll
    for (int mi = 0; mi < 2; mi++)
        #pragma unroll
        for (int ni = 0; ni < 2; ni++)
            #pragma unroll
            for (int h = 0; h < 2; h++)
                #pragma unroll
                for (int q = 0; q < 2; q++) {
                    int gi = i0 + wm * 32 + mi * 16 + fr + h * 8;
                    int gj = j0 + wn * 16 + ni * 8 + fc * 2 + q;
                    float sv = acc[mi][ni][h * 2 + q] * 5.0f;  // 1/TEMPERATURE
                    float e = __expf(sv);
                    if (gj != gi) dR[mi][h] += e;
                    if (pmask[gi * BSZ + gj] != 0) { pR[mi][h] += sv; cR[mi][h] += 1.0f; }
                    if (!diag) {
                        dC[ni][q] += e;
                        if (pmask[gj * BSZ + gi] != 0) { pC[ni][q] += sv; cC[ni][q] += 1.0f; }
                    }
                }
    // row reduce over fc lanes (width 4)
    #pragma unroll
    for (int mi = 0; mi < 2; mi++)
        #pragma unroll
        for (int h = 0; h < 2; h++) {
            #pragma unroll
            for (int o = 2; o >= 1; o >>= 1) {
                dR[mi][h] += __shfl_down_sync(0xffffffffu, dR[mi][h], o, 4);
                pR[mi][h] += __shfl_down_sync(0xffffffffu, pR[mi][h], o, 4);
                cR[mi][h] += __shfl_down_sync(0xffffffffu, cR[mi][h], o, 4);
            }
            if (fc == 0) {
                int gi = i0 + wm * 32 + mi * 16 + fr + h * 8;
                atomicAdd(&g_denom[gi], dR[mi][h]);
                atomicAdd(&g_pos[gi],   pR[mi][h]);
                atomicAdd(&g_cnt[gi],   cR[mi][h]);
            }
        }
    // col reduce over fr lanes (xor 4,8,16), then smem, then flush
    if (!diag) {
        #pragma unroll
        for (int ni = 0; ni < 2; ni++)
            #pragma unroll
            for (int q = 0; q < 2; q++) {
                #pragma unroll
                for (int o = 16; o >= 4; o >>= 1) {
                    dC[ni][q] += __shfl_xor_sync(0xffffffffu, dC[ni][q], o);
                    pC[ni][q] += __shfl_xor_sync(0xffffffffu, pC[ni][q], o);
                    cC[ni][q] += __shfl_xor_sync(0xffffffffu, cC[ni][q], o);
                }
                if (fr == 0) {
                    int lc = wn * 16 + ni * 8 + fc * 2 + q;
                    atomicAdd(&sCd[lc], dC[ni][q]);
                    atomicAdd(&sCp[lc], pC[ni][q]);
                    atomicAdd(&sCc[lc], cC[ni][q]);
                }
            }
        __syncthreads();
        if (tid < 64) {
            atomicAdd(&g_denom[j0 + tid], sCd[tid]);
            atomicAdd(&g_pos[j0 + tid],   sCp[tid]);
            atomicAdd(&g_cnt[j0 + tid],   sCc[tid]);
        }
    }
}

// ---------------- final combine ----------------
__global__ void k_combine(float* __restrict__ out) {
    int tid = threadIdx.x;               // 256 threads
    float cont = 0.f;
    for (int i = tid; i < BSZ; i += 256)
        cont += logf(g_denom[i]) - g_pos[i] / fmaxf(g_cnt[i], 1.0f);
    #pragma unroll
    for (int o = 16; o >= 1; o >>= 1)
        cont += __shfl_xor_sync(0xffffffffu, cont, o);
    __shared__ float r0[8];
    if ((tid & 31) == 0) r0[tid >> 5] = cont;
    __syncthreads();
    if (tid == 0) {
        float cT = 0.f;
        #pragma unroll
        for (int i = 0; i < 8; i++) cT += r0[i];
        float quant = g_quant / ((float)BSZ * (float)HD);
        out[0] = cT / (float)BSZ + 0.5f * g_ST + 0.01f * quant;
    }
}

// ---------------- launch ----------------
extern "C" void kernel_launch(void* const* d_in, const int* in_sizes, int n_in,
                              void* d_out, int out_size) {
    const float* logits = (const float*)d_in[0];
    const float* hash   = (const float*)d_in[1];
    const float* teach  = (const float*)d_in[2];
    const int*   pmask  = (const int*)d_in[3];
    float* out = (float*)d_out;

    float* p_Ht; cudaGetSymbolAddress((void**)&p_Ht, g_Ht);
    float* p_Tt; cudaGetSymbolAddress((void**)&p_Tt, g_Tt);
    float* p_GH; cudaGetSymbolAddress((void**)&p_GH, g_GH);
    float* p_C;  cudaGetSymbolAddress((void**)&p_C,  g_C);

    k_zero<<<512, 256>>>();
    k_norm_logits<<<BSZ, 128>>>(logits);
    k_tnorm<<<BSZ, 256>>>(teach);
    k_transpose<<<dim3(HD / 32, BSZ / 32), dim3(32, 8)>>>(hash, p_Ht, BSZ, HD, 0);
    k_transpose<<<dim3(TDIM / 32, BSZ / 32), dim3(32, 8)>>>(teach, p_Tt, BSZ, TDIM, 1);
    // G_H = H^T H : 128x128, split-K 32
    k_gemm<<<dim3(2, 2, 32), 256>>>(p_Ht, p_Ht, p_GH, HD, 128);
    // C = H^T T : 128x768, split-K 16
    k_gemm<<<dim3(2, 12, 16), 256>>>(p_Ht, p_Tt, p_C, TDIM, 256);
    // T^T T upper triangle : 78 tiles, split-K 8
    k_gemm_tri<<<dim3(78, 1, 8), 256>>>(512);
    k_sq3<<<512, 256>>>();
    // contrastive: 2080 upper-triangle 64-tiles
    k_cont<<<2080, 256>>>(pmask);
    k_combine<<<1, 256>>>(out);
}

// round 8
// speedup vs baseline: 1.6753x; 1.0349x over previous
#include <cuda_runtime.h>
#include <math.h>

#define BSZ 4096
#define HD  128
#define TDIM 768

// ---------------- device scratch ----------------
__device__ float g_LN[BSZ * HD];        // normalized logits  [B][128]
__device__ float g_Tn[BSZ];             // teacher row inv-norms
__device__ float g_Ht[HD * BSZ];        // hash^T   [128][4096]
__device__ float g_Tt[TDIM * BSZ];      // normalized teacher^T [768][4096]
__device__ float g_GH[HD * HD];         // H^T H
__device__ float g_C [HD * TDIM];       // H^T T
__device__ float g_TT[TDIM * TDIM];     // T^T T (upper triangle valid)
__device__ unsigned g_bm[BSZ * BSZ / 32];  // positive mask bits, [4096][128] u32
__device__ float g_denom[BSZ];
__device__ float g_pos[BSZ];
__device__ float g_cnt[BSZ];
__device__ float g_quant;
__device__ float g_ST;

__device__ __forceinline__ void mma_tf32(float* d, const unsigned* a, const unsigned* b) {
    asm volatile(
        "mma.sync.aligned.m16n8k8.row.col.f32.tf32.tf32.f32 "
        "{%0,%1,%2,%3}, {%4,%5,%6,%7}, {%8,%9}, {%0,%1,%2,%3};"
        : "+f"(d[0]), "+f"(d[1]), "+f"(d[2]), "+f"(d[3])
        : "r"(a[0]), "r"(a[1]), "r"(a[2]), "r"(a[3]), "r"(b[0]), "r"(b[1]));
}

// ---------------- zero accumulators ----------------
__global__ void k_zero() {
    int i = blockIdx.x * 256 + threadIdx.x;
    int n = gridDim.x * 256;
    for (int j = i; j < TDIM * TDIM; j += n) g_TT[j] = 0.f;
    for (int j = i; j < HD * TDIM;  j += n) g_C[j]  = 0.f;
    if (i < HD * HD) g_GH[i] = 0.f;
    if (i < BSZ) { g_denom[i] = 0.f; g_pos[i] = 0.f; g_cnt[i] = 0.f; }
    if (i == 0) { g_quant = 0.f; g_ST = 0.f; }
}

// ---------------- normalize logits + quant partial ----------------
__global__ void k_norm_logits(const float* __restrict__ x) {
    int row = blockIdx.x;
    int t = threadIdx.x;                 // 128 threads
    float v = x[row * HD + t];
    float ss = v * v;
    float q = fabsf(fabsf(v) - 1.0f);
    #pragma unroll
    for (int o = 16; o >= 1; o >>= 1) {
        ss += __shfl_xor_sync(0xffffffffu, ss, o);
        q  += __shfl_xor_sync(0xffffffffu, q, o);
    }
    __shared__ float sred[4], qred[4];
    __shared__ float sinv;
    int w = t >> 5, l = t & 31;
    if (l == 0) { sred[w] = ss; qred[w] = q; }
    __syncthreads();
    if (t == 0) {
        float tot = sred[0] + sred[1] + sred[2] + sred[3];
        float qt  = qred[0] + qred[1] + qred[2] + qred[3];
        atomicAdd(&g_quant, qt);
        sinv = 1.0f / fmaxf(sqrtf(tot), 1e-12f);
    }
    __syncthreads();
    g_LN[row * HD + t] = v * sinv;
}

// ---------------- mask -> bitmask (coalesced ballot) ----------------
__global__ void k_bits(const int* __restrict__ pmask) {
    int warp = (blockIdx.x * blockDim.x + threadIdx.x) >> 5;   // 16384 warps
    int lane = threadIdx.x & 31;
    long base = (long)warp * 1024;
    unsigned myword = 0;
    #pragma unroll
    for (int s = 0; s < 32; s++) {
        int v = pmask[base + s * 32 + lane];
        unsigned b = __ballot_sync(0xffffffffu, v != 0);
        if (lane == s) myword = b;
    }
    g_bm[base / 32 + lane] = myword;     // coalesced 128B per warp
}

// ---------------- teacher row inv norms ----------------
__global__ void k_tnorm(const float* __restrict__ x) {
    int row = blockIdx.x;
    int t = threadIdx.x;                 // 256 threads
    float v0 = x[row * TDIM + t];
    float v1 = x[row * TDIM + 256 + t];
    float v2 = x[row * TDIM + 512 + t];
    float ss = v0 * v0 + v1 * v1 + v2 * v2;
    #pragma unroll
    for (int o = 16; o >= 1; o >>= 1) ss += __shfl_xor_sync(0xffffffffu, ss, o);
    __shared__ float sred[8];
    if ((t & 31) == 0) sred[t >> 5] = ss;
    __syncthreads();
    if (t == 0) {
        float tot = 0.f;
        #pragma unroll
        for (int i = 0; i < 8; i++) tot += sred[i];
        g_Tn[row] = 1.0f / fmaxf(sqrtf(tot), 1e-12f);
    }
}

// ---------------- tiled transpose (optional row scaling) ----------------
__global__ void k_transpose(const float* __restrict__ src, float* __restrict__ dst,
                            int R, int C, int scaled) {
    __shared__ float t[32][33];
    int c0 = blockIdx.x * 32, r0 = blockIdx.y * 32;
    int x = threadIdx.x, y = threadIdx.y;   // block (32, 8)
    #pragma unroll
    for (int i = 0; i < 32; i += 8) {
        float v = src[(r0 + y + i) * C + c0 + x];
        if (scaled) v *= g_Tn[r0 + y + i];
        t[y + i][x] = v;
    }
    __syncthreads();
    #pragma unroll
    for (int i = 0; i < 32; i += 8) dst[(c0 + y + i) * R + r0 + x] = t[x][y + i];
}

// ======== 64x64 double-buffered mma tile core, K-chunk 32 ========
// smem: unsigned [2][64][36]; 8 warps = 2(wm) x 4(wn); warp tile 32x16

#define LDG_TILES(A4expr, B4expr)                                           \
    do {                                                                    \
        _Pragma("unroll")                                                   \
        for (int s = 0; s < 2; s++) {                                       \
            int idx = tid + s * 256;                                        \
            int r = idx >> 3, c8 = idx & 7;                                 \
            ra[s] = (A4expr);                                               \
            rb[s] = (B4expr);                                               \
        }                                                                   \
    } while (0)

#define STS_TILES(st)                                                       \
    do {                                                                    \
        _Pragma("unroll")                                                   \
        for (int s = 0; s < 2; s++) {                                       \
            int idx = tid + s * 256;                                        \
            int r = idx >> 3, c8 = idx & 7;                                 \
            *(float4*)&As[st][r][c8 * 4] = ra[s];                           \
            *(float4*)&Bs[st][r][c8 * 4] = rb[s];                           \
        }                                                                   \
    } while (0)

#define MMA_CHUNK(st)                                                       \
    do {                                                                    \
        _Pragma("unroll")                                                   \
        for (int kk = 0; kk < 4; kk++) {                                    \
            int kb = kk * 8;                                                \
            unsigned af[2][4], bf[2][2];                                    \
            _Pragma("unroll")                                               \
            for (int mi = 0; mi < 2; mi++) {                                \
                int rr = wm * 32 + mi * 16 + fr;                            \
                af[mi][0] = As[st][rr][kb + fc];                            \
                af[mi][1] = As[st][rr + 8][kb + fc];                        \
                af[mi][2] = As[st][rr][kb + fc + 4];                        \
                af[mi][3] = As[st][rr + 8][kb + fc + 4];                    \
            }                                                               \
            _Pragma("unroll")                                               \
            for (int ni = 0; ni < 2; ni++) {                                \
                int rn = wn * 16 + ni * 8 + fr;                             \
                bf[ni][0] = Bs[st][rn][kb + fc];                            \
                bf[ni][1] = Bs[st][rn][kb + fc + 4];                        \
            }                                                               \
            _Pragma("unroll")                                               \
            for (int mi = 0; mi < 2; mi++)                                  \
                _Pragma("unroll")                                           \
                for (int ni = 0; ni < 2; ni++)                              \
                    mma_tf32(acc[mi][ni], af[mi], bf[ni]);                  \
        }                                                                   \
    } while (0)

// ---------------- generic A*B^T GEMM (k-contig operands), split-K ----------
__global__ void __launch_bounds__(256) k_gemm(const float* __restrict__ A,
                                              const float* __restrict__ Bm,
                                              float* __restrict__ out, int ldo,
                                              int kPer) {
    __shared__ __align__(16) unsigned As[2][64][36];
    __shared__ __align__(16) unsigned Bs[2][64][36];
    int m0 = blockIdx.x * 64, n0 = blockIdx.y * 64;
    int kBeg = blockIdx.z * kPer;
    int tid = threadIdx.x, lane = tid & 31, w = tid >> 5;
    int wm = w & 1, wn = w >> 1;
    int fr = lane >> 2, fc = lane & 3;
    const float4* A4 = (const float4*)A;    // row stride 1024 float4
    const float4* B4 = (const float4*)Bm;
    float acc[2][2][4] = {};
    float4 ra[2], rb[2];
    int nCh = kPer >> 5;
    int kcur = kBeg;
    LDG_TILES(A4[(m0 + r) * 1024 + (kcur >> 2) + c8],
              B4[(n0 + r) * 1024 + (kcur >> 2) + c8]);
    STS_TILES(0);
    __syncthreads();
    for (int c = 0; c < nCh; c++) {
        int st = c & 1;
        if (c + 1 < nCh) {
            kcur = kBeg + (c + 1) * 32;
            LDG_TILES(A4[(m0 + r) * 1024 + (kcur >> 2) + c8],
                      B4[(n0 + r) * 1024 + (kcur >> 2) + c8]);
        }
        MMA_CHUNK(st);
        if (c + 1 < nCh) STS_TILES(1 - st);
        __syncthreads();
    }
    #pragma unroll
    for (int mi = 0; mi < 2; mi++)
        #pragma unroll
        for (int ni = 0; ni < 2; ni++)
            #pragma unroll
            for (int h = 0; h < 2; h++)
                #pragma unroll
                for (int q = 0; q < 2; q++) {
                    int gi = m0 + wm * 32 + mi * 16 + fr + h * 8;
                    int gj = n0 + wn * 16 + ni * 8 + fc * 2 + q;
                    atomicAdd(&out[gi * ldo + gj], acc[mi][ni][h * 2 + q]);
                }
}

// ---------------- T^T T upper-triangle tiles ----------------
__global__ void __launch_bounds__(256) k_gemm_tri(int kPer) {
    __shared__ __align__(16) unsigned As[2][64][36];
    __shared__ __align__(16) unsigned Bs[2][64][36];
    int t = blockIdx.x, tm = 0;                 // 12x12 tiles, upper = 78
    while (t >= 12 - tm) { t -= 12 - tm; tm++; }
    int m0 = tm * 64, n0 = (tm + t) * 64;
    int kBeg = blockIdx.z * kPer;
    int tid = threadIdx.x, lane = tid & 31, w = tid >> 5;
    int wm = w & 1, wn = w >> 1;
    int fr = lane >> 2, fc = lane & 3;
    const float4* A4 = (const float4*)g_Tt;
    float acc[2][2][4] = {};
    float4 ra[2], rb[2];
    int nCh = kPer >> 5;
    int kcur = kBeg;
    LDG_TILES(A4[(m0 + r) * 1024 + (kcur >> 2) + c8],
              A4[(n0 + r) * 1024 + (kcur >> 2) + c8]);
    STS_TILES(0);
    __syncthreads();
    for (int c = 0; c < nCh; c++) {
        int st = c & 1;
        if (c + 1 < nCh) {
            kcur = kBeg + (c + 1) * 32;
            LDG_TILES(A4[(m0 + r) * 1024 + (kcur >> 2) + c8],
                      A4[(n0 + r) * 1024 + (kcur >> 2) + c8]);
        }
        MMA_CHUNK(st);
        if (c + 1 < nCh) STS_TILES(1 - st);
        __syncthreads();
    }
    #pragma unroll
    for (int mi = 0; mi < 2; mi++)
        #pragma unroll
        for (int ni = 0; ni < 2; ni++)
            #pragma unroll
            for (int h = 0; h < 2; h++)
                #pragma unroll
                for (int q = 0; q < 2; q++) {
                    int gi = m0 + wm * 32 + mi * 16 + fr + h * 8;
                    int gj = n0 + wn * 16 + ni * 8 + fc * 2 + q;
                    atomicAdd(&g_TT[gi * TDIM + gj], acc[mi][ni][h * 2 + q]);
                }
}

// ---------------- distill square-reduce ----------------
__global__ void k_sq3() {
    int i = blockIdx.x * 256 + threadIdx.x;
    int n = gridDim.x * 256;
    float s = 0.f;
    for (int j = i; j < HD * HD; j += n) {
        float v = g_GH[j]; s += v * v * (1.f / (128.f * 128.f));
    }
    for (int j = i; j < HD * TDIM; j += n) {
        float v = g_C[j]; s -= 2.f * v * v * (1.f / 128.f);
    }
    for (int j = i; j < TDIM * TDIM; j += n) {
        int r = j / TDIM, c = j % TDIM;
        if (c < r) continue;
        float v = g_TT[j];
        s += (c == r) ? v * v : 2.f * v * v;
    }
    #pragma unroll
    for (int o = 16; o >= 1; o >>= 1) s += __shfl_xor_sync(0xffffffffu, s, o);
    __shared__ float red[8];
    if ((threadIdx.x & 31) == 0) red[threadIdx.x >> 5] = s;
    __syncthreads();
    if (threadIdx.x == 0) {
        float tot = 0.f;
        #pragma unroll
        for (int k = 0; k < 8; k++) tot += red[k];
        atomicAdd(&g_ST, tot / ((float)BSZ * (float)BSZ));
    }
}

// ---------------- contrastive: symmetric upper-tri tiles, bitmask ----------
__global__ void __launch_bounds__(256) k_cont() {
    __shared__ __align__(16) unsigned As[2][64][36];
    __shared__ __align__(16) unsigned Bs[2][64][36];
    __shared__ unsigned srow[64][2], scol[64][2];
    __shared__ float sCd[64], sCp[64], sCc[64];
    int t = blockIdx.x, tm = 0;                 // 64x64 tiles, upper = 2080
    while (t >= 64 - tm) { t -= 64 - tm; tm++; }
    int i0 = tm * 64, j0 = (tm + t) * 64;
    bool diag = (i0 == j0);
    int tid = threadIdx.x, lane = tid & 31, w = tid >> 5;
    int wm = w & 1, wn = w >> 1;
    int fr = lane >> 2, fc = lane & 3;
    if (tid < 64) { sCd[tid] = 0.f; sCp[tid] = 0.f; sCc[tid] = 0.f; }
    // mask bit-words for this tile (hidden behind the mma mainloop)
    if (tid < 128) {
        int r = tid >> 1, wd = tid & 1;
        srow[r][wd] = g_bm[(i0 + r) * (BSZ / 32) + (j0 >> 5) + wd];
    } else if (tid < 256) {
        int r = (tid - 128) >> 1, wd = tid & 1;
        scol[r][wd] = g_bm[(j0 + r) * (BSZ / 32) + (i0 >> 5) + wd];
    }
    const float4* LN4 = (const float4*)g_LN;   // row stride = 32 float4
    float acc[2][2][4] = {};
    float4 ra[2], rb[2];
    LDG_TILES(LN4[(i0 + r) * 32 + c8], LN4[(j0 + r) * 32 + c8]);
    STS_TILES(0);
    __syncthreads();
    #pragma unroll
    for (int c = 0; c < 4; c++) {
        int st = c & 1;
        if (c + 1 < 4) {
            LDG_TILES(LN4[(i0 + r) * 32 + (c + 1) * 8 + c8],
                      LN4[(j0 + r) * 32 + (c + 1) * 8 + c8]);
        }
        MMA_CHUNK(st);
        if (c + 1 < 4) STS_TILES(1 - st);
        __syncthreads();
    }

    // ---- epilogue: exp/denom + bitmask positives (both orientations) ----
    float dR[2][2] = {}, pR[2][2] = {}, cR[2][2] = {};
    float dC[2][2] = {}, pC[2][2] = {}, cC[2][2] = {};
    #pragma unroll
    for (int mi = 0; mi < 2; mi++)
        #pragma unroll
        for (int ni = 0; ni < 2; ni++)
            #pragma unroll
            for (int h = 0; h < 2; h++)
                #pragma unroll
                for (int q = 0; q < 2; q++) {
                    int li = wm * 32 + mi * 16 + fr + h * 8;
                    int lj = wn * 16 + ni * 8 + fc * 2 + q;
                    float sv = acc[mi][ni][h * 2 + q] * 5.0f;  // 1/TEMPERATURE
                    float e = __expf(sv);
                    if (!diag || li != lj) dR[mi][h] += e;
                    if ((srow[li][wn >> 1] >> (lj & 31)) & 1) {
                        pR[mi][h] += sv; cR[mi][h] += 1.0f;
                    }
                    if (!diag) {
                        dC[ni][q] += e;
                        if ((scol[lj][wm] >> (li & 31)) & 1) {
                            pC[ni][q] += sv; cC[ni][q] += 1.0f;
                        }
                    }
                }
    // row reduce over fc lanes (width 4)
    #pragma unroll
    for (int mi = 0; mi < 2; mi++)
        #pragma unroll
        for (int h = 0; h < 2; h++) {
            #pragma unroll
            for (int o = 2; o >= 1; o >>= 1) {
                dR[mi][h] += __shfl_down_sync(0xffffffffu, dR[mi][h], o, 4);
                pR[mi][h] += __shfl_down_sync(0xffffffffu, pR[mi][h], o, 4);
                cR[mi][h] += __shfl_down_sync(0xffffffffu, cR[mi][h], o, 4);
            }
            if (fc == 0) {
                int gi = i0 + wm * 32 + mi * 16 + fr + h * 8;
                atomicAdd(&g_denom[gi], dR[mi][h]);
                atomicAdd(&g_pos[gi],   pR[mi][h]);
                atomicAdd(&g_cnt[gi],   cR[mi][h]);
            }
        }
    // col reduce over fr lanes (xor 4,8,16), then smem, then flush
    if (!diag) {
        #pragma unroll
        for (int ni = 0; ni < 2; ni++)
            #pragma unroll
            for (int q = 0; q < 2; q++) {
                #pragma unroll
                for (int o = 16; o >= 4; o >>= 1) {
                    dC[ni][q] += __shfl_xor_sync(0xffffffffu, dC[ni][q], o);
                    pC[ni][q] += __shfl_xor_sync(0xffffffffu, pC[ni][q], o);
                    cC[ni][q] += __shfl_xor_sync(0xffffffffu, cC[ni][q], o);
                }
                if (fr == 0) {
                    int lc = wn * 16 + ni * 8 + fc * 2 + q;
                    atomicAdd(&sCd[lc], dC[ni][q]);
                    atomicAdd(&sCp[lc], pC[ni][q]);
                    atomicAdd(&sCc[lc], cC[ni][q]);
                }
            }
        __syncthreads();
        if (tid < 64) {
            atomicAdd(&g_denom[j0 + tid], sCd[tid]);
            atomicAdd(&g_pos[j0 + tid],   sCp[tid]);
            atomicAdd(&g_cnt[j0 + tid],   sCc[tid]);
        }
    }
}

// ---------------- final combine ----------------
__global__ void k_combine(float* __restrict__ out) {
    int tid = threadIdx.x;               // 256 threads
    float cont = 0.f;
    for (int i = tid; i < BSZ; i += 256)
        cont += logf(g_denom[i]) - g_pos[i] / fmaxf(g_cnt[i], 1.0f);
    #pragma unroll
    for (int o = 16; o >= 1; o >>= 1)
        cont += __shfl_xor_sync(0xffffffffu, cont, o);
    __shared__ float r0[8];
    if ((tid & 31) == 0) r0[tid >> 5] = cont;
    __syncthreads();
    if (tid == 0) {
        float cT = 0.f;
        #pragma unroll
        for (int i = 0; i < 8; i++) cT += r0[i];
        float quant = g_quant / ((float)BSZ * (float)HD);
        out[0] = cT / (float)BSZ + 0.5f * g_ST + 0.01f * quant;
    }
}

// ---------------- launch ----------------
extern "C" void kernel_launch(void* const* d_in, const int* in_sizes, int n_in,
                              void* d_out, int out_size) {
    const float* logits = (const float*)d_in[0];
    const float* hash   = (const float*)d_in[1];
    const float* teach  = (const float*)d_in[2];
    const int*   pmask  = (const int*)d_in[3];
    float* out = (float*)d_out;

    float* p_Ht; cudaGetSymbolAddress((void**)&p_Ht, g_Ht);
    float* p_Tt; cudaGetSymbolAddress((void**)&p_Tt, g_Tt);
    float* p_GH; cudaGetSymbolAddress((void**)&p_GH, g_GH);
    float* p_C;  cudaGetSymbolAddress((void**)&p_C,  g_C);

    k_zero<<<512, 256>>>();                                              // 1
    k_norm_logits<<<BSZ, 128>>>(logits);                                 // 2
    k_bits<<<2048, 256>>>(pmask);                                        // 3
    k_tnorm<<<BSZ, 256>>>(teach);                                        // 4
    k_transpose<<<dim3(HD / 32, BSZ / 32), dim3(32, 8)>>>(hash, p_Ht, BSZ, HD, 0);  // 5
    // contrastive: 2080 upper-triangle 64-tiles  (6th launch -> ncu captures this)
    k_cont<<<2080, 256>>>();                                             // 6
    k_transpose<<<dim3(TDIM / 32, BSZ / 32), dim3(32, 8)>>>(teach, p_Tt, BSZ, TDIM, 1);
    // G_H = H^T H : 128x128, split-K 32
    k_gemm<<<dim3(2, 2, 32), 256>>>(p_Ht, p_Ht, p_GH, HD, 128);
    // C = H^T T : 128x768, split-K 16
    k_gemm<<<dim3(2, 12, 16), 256>>>(p_Ht, p_Tt, p_C, TDIM, 256);
    // T^T T upper triangle : 78 tiles, split-K 16
    k_gemm_tri<<<dim3(78, 1, 16), 256>>>(256);
    k_sq3<<<512, 256>>>();
    k_combine<<<1, 256>>>(out);
}

// round 9
// speedup vs baseline: 1.9904x; 1.1881x over previous
#include <cuda_runtime.h>
#include <cuda_bf16.h>
#include <math.h>

#define BSZ 4096
#define HD  128
#define TDIM 768

// ---------------- device scratch ----------------
__device__ __align__(16) float g_LN[BSZ * HD];          // normalized logits fp32
__device__ __align__(16) __nv_bfloat16 g_LNh[BSZ * HD]; // normalized logits bf16
__device__ float g_Tn[BSZ];                              // teacher row inv-norms
__device__ __align__(16) __nv_bfloat16 g_Ht16[HD * BSZ];   // hash^T bf16 [128][4096]
__device__ __align__(16) __nv_bfloat16 g_Tt16[TDIM * BSZ]; // norm teacher^T bf16
__device__ float g_GH[HD * HD];
__device__ float g_C [HD * TDIM];
__device__ float g_TT[TDIM * TDIM];
__device__ unsigned g_bm[BSZ * BSZ / 32];  // mask bits [4096][128] u32
__device__ float g_denom[BSZ];
__device__ float g_pos[BSZ];
__device__ float g_cnt[BSZ];
__device__ float g_quant;
__device__ float g_ST;

__device__ __forceinline__ void mma_bf16(float* d, const unsigned* a, const unsigned* b) {
    asm volatile(
        "mma.sync.aligned.m16n8k16.row.col.f32.bf16.bf16.f32 "
        "{%0,%1,%2,%3}, {%4,%5,%6,%7}, {%8,%9}, {%0,%1,%2,%3};"
        : "+f"(d[0]), "+f"(d[1]), "+f"(d[2]), "+f"(d[3])
        : "r"(a[0]), "r"(a[1]), "r"(a[2]), "r"(a[3]), "r"(b[0]), "r"(b[1]));
}

// ---------------- mask -> bitmask + zero accumulators ----------------
__global__ void k_bits(const int* __restrict__ pmask) {
    // zeroing (grid-stride over 2048*256 threads)
    int gi = blockIdx.x * 256 + threadIdx.x;
    int n = gridDim.x * 256;
    for (int j = gi; j < TDIM * TDIM; j += n) g_TT[j] = 0.f;
    for (int j = gi; j < HD * TDIM;  j += n) g_C[j]  = 0.f;
    if (gi < HD * HD) g_GH[gi] = 0.f;
    if (gi < BSZ) g_denom[gi] = 0.f;
    if (gi == 0) { g_quant = 0.f; g_ST = 0.f; }
    // ballot bitmask build (coalesced)
    int warp = gi >> 5;                  // 16384 warps
    int lane = threadIdx.x & 31;
    long base = (long)warp * 1024;
    unsigned myword = 0;
    #pragma unroll
    for (int s = 0; s < 32; s++) {
        int v = pmask[base + s * 32 + lane];
        unsigned b = __ballot_sync(0xffffffffu, v != 0);
        if (lane == s) myword = b;
    }
    g_bm[base / 32 + lane] = myword;
}

// ---------------- normalize logits + quant partial (fp32 + bf16 out) --------
__global__ void k_norm_logits(const float* __restrict__ x) {
    int row = blockIdx.x;
    int t = threadIdx.x;                 // 128 threads
    float v = x[row * HD + t];
    float ss = v * v;
    float q = fabsf(fabsf(v) - 1.0f);
    #pragma unroll
    for (int o = 16; o >= 1; o >>= 1) {
        ss += __shfl_xor_sync(0xffffffffu, ss, o);
        q  += __shfl_xor_sync(0xffffffffu, q, o);
    }
    __shared__ float sred[4], qred[4];
    __shared__ float sinv;
    int w = t >> 5, l = t & 31;
    if (l == 0) { sred[w] = ss; qred[w] = q; }
    __syncthreads();
    if (t == 0) {
        float tot = sred[0] + sred[1] + sred[2] + sred[3];
        float qt  = qred[0] + qred[1] + qred[2] + qred[3];
        atomicAdd(&g_quant, qt);
        sinv = 1.0f / fmaxf(sqrtf(tot), 1e-12f);
    }
    __syncthreads();
    float nv = v * sinv;
    g_LN[row * HD + t] = nv;
    g_LNh[row * HD + t] = __float2bfloat16(nv);
}

// ---------------- positives: warp-per-row bitmask scan, exact fp32 ----------
__global__ void k_posbits() {
    int warp = (blockIdx.x * blockDim.x + threadIdx.x) >> 5;   // 4096 warps
    int lane = threadIdx.x & 31;
    int row = warp;
    const float4* LN4 = (const float4*)g_LN;   // row stride 32 float4
    float4 a = LN4[row * 32 + lane];
    float ps = 0.f;
    int cnt = 0;
    #pragma unroll
    for (int g = 0; g < 4; g++) {
        unsigned wrd = g_bm[row * 128 + g * 32 + lane];
        unsigned act = __ballot_sync(0xffffffffu, wrd != 0);
        while (act) {
            int src = __ffs(act) - 1; act &= act - 1;
            unsigned w2 = __shfl_sync(0xffffffffu, wrd, src);
            int base = (g * 32 + src) * 32;
            while (w2) {
                int b = __ffs(w2) - 1; w2 &= w2 - 1;
                int j = base + b;
                float4 bb = LN4[j * 32 + lane];
                float d = a.x * bb.x + a.y * bb.y + a.z * bb.z + a.w * bb.w;
                #pragma unroll
                for (int o = 16; o >= 1; o >>= 1)
                    d += __shfl_xor_sync(0xffffffffu, d, o);
                ps += d; cnt++;
            }
        }
    }
    if (lane == 0) { g_pos[row] = ps * 5.0f; g_cnt[row] = (float)cnt; }
}

// ---------------- teacher row inv norms ----------------
__global__ void k_tnorm(const float* __restrict__ x) {
    int row = blockIdx.x;
    int t = threadIdx.x;                 // 256 threads
    float v0 = x[row * TDIM + t];
    float v1 = x[row * TDIM + 256 + t];
    float v2 = x[row * TDIM + 512 + t];
    float ss = v0 * v0 + v1 * v1 + v2 * v2;
    #pragma unroll
    for (int o = 16; o >= 1; o >>= 1) ss += __shfl_xor_sync(0xffffffffu, ss, o);
    __shared__ float sred[8];
    if ((t & 31) == 0) sred[t >> 5] = ss;
    __syncthreads();
    if (t == 0) {
        float tot = 0.f;
        #pragma unroll
        for (int i = 0; i < 8; i++) tot += sred[i];
        g_Tn[row] = 1.0f / fmaxf(sqrtf(tot), 1e-12f);
    }
}

// ---------------- tiled transpose -> bf16 (optional row scaling) ------------
__global__ void k_transpose16(const float* __restrict__ src, __nv_bfloat16* __restrict__ dst,
                              int R, int C, int scaled) {
    __shared__ float t[32][33];
    int c0 = blockIdx.x * 32, r0 = blockIdx.y * 32;
    int x = threadIdx.x, y = threadIdx.y;   // block (32, 8)
    #pragma unroll
    for (int i = 0; i < 32; i += 8) {
        float v = src[(r0 + y + i) * C + c0 + x];
        if (scaled) v *= g_Tn[r0 + y + i];
        t[y + i][x] = v;
    }
    __syncthreads();
    #pragma unroll
    for (int i = 0; i < 32; i += 8)
        dst[(c0 + y + i) * R + r0 + x] = __float2bfloat16(t[x][y + i]);
}

// ======== 64x64 double-buffered bf16 mma core, K-chunk 32 ========
// smem u32 tiles [2][64][20] (u32 = 2 bf16); 8 warps = 2(wm) x 4(wn); warp 32x16
// mma m16n8k16: per chunk 2 k-steps x 4 frag-mmas

#define LDG16(Aexpr, Bexpr)                                                 \
    do { int r = tid >> 2, c4 = tid & 3; (void)r; (void)c4;                 \
         ga = (Aexpr); gb = (Bexpr); } while (0)

#define STS16(st)                                                           \
    do { int r = tid >> 2, c4 = tid & 3;                                    \
         *(uint4*)&As16[st][r][c4 * 4] = ga;                                \
         *(uint4*)&Bs16[st][r][c4 * 4] = gb; } while (0)

#define MMA16_CHUNK(st)                                                     \
    do {                                                                    \
        _Pragma("unroll")                                                   \
        for (int kk = 0; kk < 2; kk++) {                                    \
            int kb = kk * 8;                                                \
            unsigned af[2][4], bf[2][2];                                    \
            _Pragma("unroll")                                               \
            for (int mi = 0; mi < 2; mi++) {                                \
                int rr = wm * 32 + mi * 16 + fr;                            \
                af[mi][0] = As16[st][rr][kb + fc];                          \
                af[mi][1] = As16[st][rr + 8][kb + fc];                      \
                af[mi][2] = As16[st][rr][kb + fc + 4];                      \
                af[mi][3] = As16[st][rr + 8][kb + fc + 4];                  \
            }                                                               \
            _Pragma("unroll")                                               \
            for (int ni = 0; ni < 2; ni++) {                                \
                int rn = wn * 16 + ni * 8 + fr;                             \
                bf[ni][0] = Bs16[st][rn][kb + fc];                          \
                bf[ni][1] = Bs16[st][rn][kb + fc + 4];                      \
            }                                                               \
            _Pragma("unroll")                                               \
            for (int mi = 0; mi < 2; mi++)                                  \
                _Pragma("unroll")                                           \
                for (int ni = 0; ni < 2; ni++)                              \
                    mma_bf16(acc[mi][ni], af[mi], bf[ni]);                  \
        }                                                                   \
    } while (0)

// ---------------- generic bf16 A*B^T GEMM (k-contig [rows][4096]) -----------
__global__ void __launch_bounds__(256) k_gemm16(const __nv_bfloat16* __restrict__ A,
                                                const __nv_bfloat16* __restrict__ Bm,
                                                float* __restrict__ out, int ldo,
                                                int kPer) {
    __shared__ __align__(16) unsigned As16[2][64][20];
    __shared__ __align__(16) unsigned Bs16[2][64][20];
    int m0 = blockIdx.x * 64, n0 = blockIdx.y * 64;
    int kBeg = blockIdx.z * kPer;
    int tid = threadIdx.x, lane = tid & 31, w = tid >> 5;
    int wm = w & 1, wn = w >> 1;
    int fr = lane >> 2, fc = lane & 3;
    const uint4* A4 = (const uint4*)A;    // row = 512 uint4 (8 bf16 each)
    const uint4* B4 = (const uint4*)Bm;
    float acc[2][2][4] = {};
    uint4 ga, gb;
    int nCh = kPer >> 5;
    LDG16(A4[(m0 + r) * 512 + (kBeg >> 3) + c4],
          B4[(n0 + r) * 512 + (kBeg >> 3) + c4]);
    STS16(0);
    __syncthreads();
    for (int c = 0; c < nCh; c++) {
        int st = c & 1;
        if (c + 1 < nCh) {
            int kc = kBeg + (c + 1) * 32;
            LDG16(A4[(m0 + r) * 512 + (kc >> 3) + c4],
                  B4[(n0 + r) * 512 + (kc >> 3) + c4]);
        }
        MMA16_CHUNK(st);
        if (c + 1 < nCh) STS16(1 - st);
        __syncthreads();
    }
    #pragma unroll
    for (int mi = 0; mi < 2; mi++)
        #pragma unroll
        for (int ni = 0; ni < 2; ni++)
            #pragma unroll
            for (int h = 0; h < 2; h++)
                #pragma unroll
                for (int q = 0; q < 2; q++) {
                    int gi = m0 + wm * 32 + mi * 16 + fr + h * 8;
                    int gj = n0 + wn * 16 + ni * 8 + fc * 2 + q;
                    atomicAdd(&out[gi * ldo + gj], acc[mi][ni][h * 2 + q]);
                }
}

// ---------------- T^T T upper-triangle tiles (bf16) ----------------
__global__ void __launch_bounds__(256) k_gemm_tri16(int kPer) {
    __shared__ __align__(16) unsigned As16[2][64][20];
    __shared__ __align__(16) unsigned Bs16[2][64][20];
    int t = blockIdx.x, tm = 0;                 // 12x12 tiles, upper = 78
    while (t >= 12 - tm) { t -= 12 - tm; tm++; }
    int m0 = tm * 64, n0 = (tm + t) * 64;
    int kBeg = blockIdx.z * kPer;
    int tid = threadIdx.x, lane = tid & 31, w = tid >> 5;
    int wm = w & 1, wn = w >> 1;
    int fr = lane >> 2, fc = lane & 3;
    const uint4* A4 = (const uint4*)g_Tt16;
    float acc[2][2][4] = {};
    uint4 ga, gb;
    int nCh = kPer >> 5;
    LDG16(A4[(m0 + r) * 512 + (kBeg >> 3) + c4],
          A4[(n0 + r) * 512 + (kBeg >> 3) + c4]);
    STS16(0);
    __syncthreads();
    for (int c = 0; c < nCh; c++) {
        int st = c & 1;
        if (c + 1 < nCh) {
            int kc = kBeg + (c + 1) * 32;
            LDG16(A4[(m0 + r) * 512 + (kc >> 3) + c4],
                  A4[(n0 + r) * 512 + (kc >> 3) + c4]);
        }
        MMA16_CHUNK(st);
        if (c + 1 < nCh) STS16(1 - st);
        __syncthreads();
    }
    #pragma unroll
    for (int mi = 0; mi < 2; mi++)
        #pragma unroll
        for (int ni = 0; ni < 2; ni++)
            #pragma unroll
            for (int h = 0; h < 2; h++)
                #pragma unroll
                for (int q = 0; q < 2; q++) {
                    int gi = m0 + wm * 32 + mi * 16 + fr + h * 8;
                    int gj = n0 + wn * 16 + ni * 8 + fc * 2 + q;
                    atomicAdd(&g_TT[gi * TDIM + gj], acc[mi][ni][h * 2 + q]);
                }
}

// ---------------- distill square-reduce ----------------
__global__ void k_sq3() {
    int i = blockIdx.x * 256 + threadIdx.x;
    int n = gridDim.x * 256;
    float s = 0.f;
    for (int j = i; j < HD * HD; j += n) {
        float v = g_GH[j]; s += v * v * (1.f / (128.f * 128.f));
    }
    for (int j = i; j < HD * TDIM; j += n) {
        float v = g_C[j]; s -= 2.f * v * v * (1.f / 128.f);
    }
    for (int j = i; j < TDIM * TDIM; j += n) {
        int r = j / TDIM, c = j % TDIM;
        if (c < r) continue;
        float v = g_TT[j];
        s += (c == r) ? v * v : 2.f * v * v;
    }
    #pragma unroll
    for (int o = 16; o >= 1; o >>= 1) s += __shfl_xor_sync(0xffffffffu, s, o);
    __shared__ float red[8];
    if ((threadIdx.x & 31) == 0) red[threadIdx.x >> 5] = s;
    __syncthreads();
    if (threadIdx.x == 0) {
        float tot = 0.f;
        #pragma unroll
        for (int k = 0; k < 8; k++) tot += red[k];
        atomicAdd(&g_ST, tot / ((float)BSZ * (float)BSZ));
    }
}

// ---------------- contrastive: upper-tri bf16 tiles, denominator only -------
__global__ void __launch_bounds__(256) k_cont() {
    __shared__ __align__(16) unsigned As16[2][64][20];
    __shared__ __align__(16) unsigned Bs16[2][64][20];
    __shared__ float sCd[64];
    int t = blockIdx.x, tm = 0;                 // 64x64 tiles, upper = 2080
    while (t >= 64 - tm) { t -= 64 - tm; tm++; }
    int i0 = tm * 64, j0 = (tm + t) * 64;
    bool diag = (i0 == j0);
    int tid = threadIdx.x, lane = tid & 31, w = tid >> 5;
    int wm = w & 1, wn = w >> 1;
    int fr = lane >> 2, fc = lane & 3;
    if (tid < 64) sCd[tid] = 0.f;
    const uint4* LN4 = (const uint4*)g_LNh;   // row = 16 uint4 (128 bf16)
    float acc[2][2][4] = {};
    uint4 ga, gb;
    LDG16(LN4[(i0 + r) * 16 + c4], LN4[(j0 + r) * 16 + c4]);
    STS16(0);
    __syncthreads();
    #pragma unroll
    for (int c = 0; c < 4; c++) {
        int st = c & 1;
        if (c + 1 < 4) {
            LDG16(LN4[(i0 + r) * 16 + (c + 1) * 4 + c4],
                  LN4[(j0 + r) * 16 + (c + 1) * 4 + c4]);
        }
        MMA16_CHUNK(st);
        if (c + 1 < 4) STS16(1 - st);
        __syncthreads();
    }

    // ---- epilogue: exp sums, both orientations ----
    float dR[2][2] = {}, dC[2][2] = {};
    #pragma unroll
    for (int mi = 0; mi < 2; mi++)
        #pragma unroll
        for (int ni = 0; ni < 2; ni++)
            #pragma unroll
            for (int h = 0; h < 2; h++)
                #pragma unroll
                for (int q = 0; q < 2; q++) {
                    int li = wm * 32 + mi * 16 + fr + h * 8;
                    int lj = wn * 16 + ni * 8 + fc * 2 + q;
                    float e = __expf(acc[mi][ni][h * 2 + q] * 5.0f);
                    if (!diag || li != lj) dR[mi][h] += e;
                    if (!diag) dC[ni][q] += e;
                }
    // row reduce over fc lanes (width 4)
    #pragma unroll
    for (int mi = 0; mi < 2; mi++)
        #pragma unroll
        for (int h = 0; h < 2; h++) {
            #pragma unroll
            for (int o = 2; o >= 1; o >>= 1)
                dR[mi][h] += __shfl_down_sync(0xffffffffu, dR[mi][h], o, 4);
            if (fc == 0)
                atomicAdd(&g_denom[i0 + wm * 32 + mi * 16 + fr + h * 8], dR[mi][h]);
        }
    // col reduce over fr lanes (xor 4,8,16)
    if (!diag) {
        #pragma unroll
        for (int ni = 0; ni < 2; ni++)
            #pragma unroll
            for (int q = 0; q < 2; q++) {
                #pragma unroll
                for (int o = 16; o >= 4; o >>= 1)
                    dC[ni][q] += __shfl_xor_sync(0xffffffffu, dC[ni][q], o);
                if (fr == 0)
                    atomicAdd(&sCd[wn * 16 + ni * 8 + fc * 2 + q], dC[ni][q]);
            }
        __syncthreads();
        if (tid < 64) atomicAdd(&g_denom[j0 + tid], sCd[tid]);
    }
}

// ---------------- final combine ----------------
__global__ void k_combine(float* __restrict__ out) {
    int tid = threadIdx.x;               // 256 threads
    float cont = 0.f;
    for (int i = tid; i < BSZ; i += 256)
        cont += logf(g_denom[i]) - g_pos[i] / fmaxf(g_cnt[i], 1.0f);
    #pragma unroll
    for (int o = 16; o >= 1; o >>= 1)
        cont += __shfl_xor_sync(0xffffffffu, cont, o);
    __shared__ float r0[8];
    if ((tid & 31) == 0) r0[tid >> 5] = cont;
    __syncthreads();
    if (tid == 0) {
        float cT = 0.f;
        #pragma unroll
        for (int i = 0; i < 8; i++) cT += r0[i];
        float quant = g_quant / ((float)BSZ * (float)HD);
        out[0] = cT / (float)BSZ + 0.5f * g_ST + 0.01f * quant;
    }
}

// ---------------- launch ----------------
extern "C" void kernel_launch(void* const* d_in, const int* in_sizes, int n_in,
                              void* d_out, int out_size) {
    const float* logits = (const float*)d_in[0];
    const float* hash   = (const float*)d_in[1];
    const float* teach  = (const float*)d_in[2];
    const int*   pmask  = (const int*)d_in[3];
    float* out = (float*)d_out;

    __nv_bfloat16* p_Ht; cudaGetSymbolAddress((void**)&p_Ht, g_Ht16);
    __nv_bfloat16* p_Tt; cudaGetSymbolAddress((void**)&p_Tt, g_Tt16);
    float* p_GH; cudaGetSymbolAddress((void**)&p_GH, g_GH);
    float* p_C;  cudaGetSymbolAddress((void**)&p_C,  g_C);

    k_bits<<<2048, 256>>>(pmask);                                        // 1 (+zero)
    k_norm_logits<<<BSZ, 128>>>(logits);                                 // 2
    k_posbits<<<512, 256>>>();                                           // 3
    k_tnorm<<<BSZ, 256>>>(teach);                                        // 4
    k_transpose16<<<dim3(HD / 32, BSZ / 32), dim3(32, 8)>>>(hash, p_Ht, BSZ, HD, 0); // 5
    k_cont<<<2080, 256>>>();                                             // 6
    k_transpose16<<<dim3(TDIM / 32, BSZ / 32), dim3(32, 8)>>>(teach, p_Tt, BSZ, TDIM, 1);
    // G_H = H^T H : split-K 32
    k_gemm16<<<dim3(2, 2, 32), 256>>>(p_Ht, p_Ht, p_GH, HD, 128);
    // C = H^T T : split-K 16
    k_gemm16<<<dim3(2, 12, 16), 256>>>(p_Ht, p_Tt, p_C, TDIM, 256);
    // T^T T upper triangle : 78 tiles, split-K 16
    k_gemm_tri16<<<dim3(78, 1, 16), 256>>>(256);
    k_sq3<<<512, 256>>>();
    k_combine<<<1, 256>>>(out);
}

// round 10
// speedup vs baseline: 2.0440x; 1.0269x over previous
#include <cuda_runtime.h>
#include <cuda_bf16.h>
#include <math.h>

#define BSZ 4096
#define HD  128
#define TDIM 768

// ---------------- device scratch ----------------
__device__ __align__(16) float g_LN[BSZ * HD];          // normalized logits fp32
__device__ __align__(16) __nv_bfloat16 g_LNh[BSZ * HD]; // normalized logits bf16
__device__ float g_Tn[BSZ];                              // teacher row inv-norms
__device__ __align__(16) __nv_bfloat16 g_Ht16[HD * BSZ];   // hash^T bf16 [128][4096]
__device__ __align__(16) __nv_bfloat16 g_Tt16[TDIM * BSZ]; // norm teacher^T bf16
__device__ float g_GH[HD * HD];
__device__ float g_C [HD * TDIM];
__device__ float g_TT[TDIM * TDIM];
__device__ unsigned g_bm[BSZ * BSZ / 32];  // mask bits [4096][128] u32
__device__ float g_denom[BSZ];
__device__ float g_pos[BSZ];
__device__ float g_cnt[BSZ];
__device__ float g_quant;
__device__ float g_ST;

__device__ __forceinline__ void mma_bf16(float* d, const unsigned* a, const unsigned* b) {
    asm volatile(
        "mma.sync.aligned.m16n8k16.row.col.f32.bf16.bf16.f32 "
        "{%0,%1,%2,%3}, {%4,%5,%6,%7}, {%8,%9}, {%0,%1,%2,%3};"
        : "+f"(d[0]), "+f"(d[1]), "+f"(d[2]), "+f"(d[3])
        : "r"(a[0]), "r"(a[1]), "r"(a[2]), "r"(a[3]), "r"(b[0]), "r"(b[1]));
}

// ---------------- mask -> bitmask + zero accumulators ----------------
__global__ void k_bits(const int* __restrict__ pmask) {
    int gi = blockIdx.x * 256 + threadIdx.x;
    int n = gridDim.x * 256;
    for (int j = gi; j < TDIM * TDIM; j += n) g_TT[j] = 0.f;
    for (int j = gi; j < HD * TDIM;  j += n) g_C[j]  = 0.f;
    if (gi < HD * HD) g_GH[gi] = 0.f;
    if (gi < BSZ) g_denom[gi] = 0.f;
    if (gi == 0) { g_quant = 0.f; g_ST = 0.f; }
    int warp = gi >> 5;                  // 16384 warps
    int lane = threadIdx.x & 31;
    long base = (long)warp * 1024;
    unsigned myword = 0;
    #pragma unroll
    for (int s = 0; s < 32; s++) {
        int v = pmask[base + s * 32 + lane];
        unsigned b = __ballot_sync(0xffffffffu, v != 0);
        if (lane == s) myword = b;
    }
    g_bm[base / 32 + lane] = myword;
}

// ---------------- normalize logits + quant partial (fp32 + bf16 out) --------
__global__ void k_norm_logits(const float* __restrict__ x) {
    int row = blockIdx.x;
    int t = threadIdx.x;                 // 128 threads
    float v = x[row * HD + t];
    float ss = v * v;
    float q = fabsf(fabsf(v) - 1.0f);
    #pragma unroll
    for (int o = 16; o >= 1; o >>= 1) {
        ss += __shfl_xor_sync(0xffffffffu, ss, o);
        q  += __shfl_xor_sync(0xffffffffu, q, o);
    }
    __shared__ float sred[4], qred[4];
    __shared__ float sinv;
    int w = t >> 5, l = t & 31;
    if (l == 0) { sred[w] = ss; qred[w] = q; }
    __syncthreads();
    if (t == 0) {
        float tot = sred[0] + sred[1] + sred[2] + sred[3];
        float qt  = qred[0] + qred[1] + qred[2] + qred[3];
        atomicAdd(&g_quant, qt);
        sinv = 1.0f / fmaxf(sqrtf(tot), 1e-12f);
    }
    __syncthreads();
    float nv = v * sinv;
    g_LN[row * HD + t] = nv;
    g_LNh[row * HD + t] = __float2bfloat16(nv);
}

// ---------------- positives: warp-per-row bitmask scan, exact fp32 ----------
__global__ void k_posbits() {
    int warp = (blockIdx.x * blockDim.x + threadIdx.x) >> 5;   // 4096 warps
    int lane = threadIdx.x & 31;
    int row = warp;
    const float4* LN4 = (const float4*)g_LN;   // row stride 32 float4
    float4 a = LN4[row * 32 + lane];
    float ps = 0.f;
    int cnt = 0;
    #pragma unroll
    for (int g = 0; g < 4; g++) {
        unsigned wrd = g_bm[row * 128 + g * 32 + lane];
        unsigned act = __ballot_sync(0xffffffffu, wrd != 0);
        while (act) {
            int src = __ffs(act) - 1; act &= act - 1;
            unsigned w2 = __shfl_sync(0xffffffffu, wrd, src);
            int base = (g * 32 + src) * 32;
            while (w2) {
                int b = __ffs(w2) - 1; w2 &= w2 - 1;
                int j = base + b;
                float4 bb = LN4[j * 32 + lane];
                float d = a.x * bb.x + a.y * bb.y + a.z * bb.z + a.w * bb.w;
                #pragma unroll
                for (int o = 16; o >= 1; o >>= 1)
                    d += __shfl_xor_sync(0xffffffffu, d, o);
                ps += d; cnt++;
            }
        }
    }
    if (lane == 0) { g_pos[row] = ps * 5.0f; g_cnt[row] = (float)cnt; }
}

// ---------------- teacher row inv norms (warp-per-row, float4) --------------
__global__ void k_tnorm(const float* __restrict__ x) {
    int gw = (blockIdx.x * blockDim.x + threadIdx.x) >> 5;   // 1024 warps
    int lane = threadIdx.x & 31;
    for (int row = gw; row < BSZ; row += 1024) {
        const float4* x4 = (const float4*)(x + row * TDIM);  // 192 float4
        float ss = 0.f;
        #pragma unroll
        for (int i = 0; i < 6; i++) {
            float4 v = x4[lane + i * 32];
            ss += v.x * v.x + v.y * v.y + v.z * v.z + v.w * v.w;
        }
        #pragma unroll
        for (int o = 16; o >= 1; o >>= 1) ss += __shfl_xor_sync(0xffffffffu, ss, o);
        if (lane == 0) g_Tn[row] = 1.0f / fmaxf(sqrtf(ss), 1e-12f);
    }
}

// ---------------- fused transposes -> bf16 (hash + scaled teacher) ----------
__global__ void k_transpose_both(const float* __restrict__ hash,
                                 const float* __restrict__ teach) {
    __shared__ float t[32][33];
    int x = threadIdx.x, y = threadIdx.y;   // block (32, 8)
    int r0 = blockIdx.y * 32;
    if (blockIdx.x < 4) {
        int c0 = blockIdx.x * 32;
        #pragma unroll
        for (int i = 0; i < 32; i += 8) t[y + i][x] = hash[(r0 + y + i) * HD + c0 + x];
        __syncthreads();
        #pragma unroll
        for (int i = 0; i < 32; i += 8)
            g_Ht16[(c0 + y + i) * BSZ + r0 + x] = __float2bfloat16(t[x][y + i]);
    } else {
        int c0 = (blockIdx.x - 4) * 32;
        #pragma unroll
        for (int i = 0; i < 32; i += 8)
            t[y + i][x] = teach[(r0 + y + i) * TDIM + c0 + x] * g_Tn[r0 + y + i];
        __syncthreads();
        #pragma unroll
        for (int i = 0; i < 32; i += 8)
            g_Tt16[(c0 + y + i) * BSZ + r0 + x] = __float2bfloat16(t[x][y + i]);
    }
}

// ======== 128x128 double-buffered bf16 mma core, K-chunk 32 ========
// smem u32 [2][128][20]; 8 warps = 2(wm) x 4(wn); warp tile 64x32; 4(mi)x4(ni)

#define LDG16(Aexpr, Bexpr)                                                 \
    do {                                                                    \
        _Pragma("unroll")                                                   \
        for (int s = 0; s < 2; s++) {                                       \
            int idx = tid + s * 256;                                        \
            int r = idx >> 2, c4 = idx & 3;                                 \
            ga[s] = (Aexpr); gb[s] = (Bexpr);                               \
        }                                                                   \
    } while (0)

#define STS16(st)                                                           \
    do {                                                                    \
        _Pragma("unroll")                                                   \
        for (int s = 0; s < 2; s++) {                                       \
            int idx = tid + s * 256;                                        \
            int r = idx >> 2, c4 = idx & 3;                                 \
            *(uint4*)&As16[st][r][c4 * 4] = ga[s];                          \
            *(uint4*)&Bs16[st][r][c4 * 4] = gb[s];                          \
        }                                                                   \
    } while (0)

#define MMA16_CHUNK(st)                                                     \
    do {                                                                    \
        _Pragma("unroll")                                                   \
        for (int kk = 0; kk < 2; kk++) {                                    \
            int kb = kk * 8;                                                \
            unsigned af[4][4], bf[4][2];                                    \
            _Pragma("unroll")                                               \
            for (int mi = 0; mi < 4; mi++) {                                \
                int rr = wm * 64 + mi * 16 + fr;                            \
                af[mi][0] = As16[st][rr][kb + fc];                          \
                af[mi][1] = As16[st][rr + 8][kb + fc];                      \
                af[mi][2] = As16[st][rr][kb + fc + 4];                      \
                af[mi][3] = As16[st][rr + 8][kb + fc + 4];                  \
            }                                                               \
            _Pragma("unroll")                                               \
            for (int ni = 0; ni < 4; ni++) {                                \
                int rn = wn * 32 + ni * 8 + fr;                             \
                bf[ni][0] = Bs16[st][rn][kb + fc];                          \
                bf[ni][1] = Bs16[st][rn][kb + fc + 4];                      \
            }                                                               \
            _Pragma("unroll")                                               \
            for (int mi = 0; mi < 4; mi++)                                  \
                _Pragma("unroll")                                           \
                for (int ni = 0; ni < 4; ni++)                              \
                    mma_bf16(acc[mi][ni], af[mi], bf[ni]);                  \
        }                                                                   \
    } while (0)

// ---------------- generic bf16 A*B^T GEMM (k-contig [rows][4096]) -----------
__global__ void __launch_bounds__(256) k_gemm16(const __nv_bfloat16* __restrict__ A,
                                                const __nv_bfloat16* __restrict__ Bm,
                                                float* __restrict__ out, int ldo,
                                                int kPer) {
    __shared__ __align__(16) unsigned As16[2][128][20];
    __shared__ __align__(16) unsigned Bs16[2][128][20];
    int m0 = blockIdx.x * 128, n0 = blockIdx.y * 128;
    int kBeg = blockIdx.z * kPer;
    int tid = threadIdx.x, lane = tid & 31, w = tid >> 5;
    int wm = w & 1, wn = w >> 1;
    int fr = lane >> 2, fc = lane & 3;
    const uint4* A4 = (const uint4*)A;    // row = 512 uint4
    const uint4* B4 = (const uint4*)Bm;
    float acc[4][4][4] = {};
    uint4 ga[2], gb[2];
    int nCh = kPer >> 5;
    LDG16(A4[(m0 + r) * 512 + (kBeg >> 3) + c4],
          B4[(n0 + r) * 512 + (kBeg >> 3) + c4]);
    STS16(0);
    __syncthreads();
    for (int c = 0; c < nCh; c++) {
        int st = c & 1;
        if (c + 1 < nCh) {
            int kc = kBeg + (c + 1) * 32;
            LDG16(A4[(m0 + r) * 512 + (kc >> 3) + c4],
                  B4[(n0 + r) * 512 + (kc >> 3) + c4]);
        }
        MMA16_CHUNK(st);
        if (c + 1 < nCh) STS16(1 - st);
        __syncthreads();
    }
    #pragma unroll
    for (int mi = 0; mi < 4; mi++)
        #pragma unroll
        for (int ni = 0; ni < 4; ni++)
            #pragma unroll
            for (int h = 0; h < 2; h++)
                #pragma unroll
                for (int q = 0; q < 2; q++) {
                    int gi = m0 + wm * 64 + mi * 16 + fr + h * 8;
                    int gj = n0 + wn * 32 + ni * 8 + fc * 2 + q;
                    atomicAdd(&out[gi * ldo + gj], acc[mi][ni][h * 2 + q]);
                }
}

// ---------------- T^T T upper-triangle 128-tiles (bf16) ----------------
__global__ void __launch_bounds__(256) k_gemm_tri16(int kPer) {
    __shared__ __align__(16) unsigned As16[2][128][20];
    __shared__ __align__(16) unsigned Bs16[2][128][20];
    int t = blockIdx.x, tm = 0;                 // 6x6 tiles, upper = 21
    while (t >= 6 - tm) { t -= 6 - tm; tm++; }
    int m0 = tm * 128, n0 = (tm + t) * 128;
    int kBeg = blockIdx.z * kPer;
    int tid = threadIdx.x, lane = tid & 31, w = tid >> 5;
    int wm = w & 1, wn = w >> 1;
    int fr = lane >> 2, fc = lane & 3;
    const uint4* A4 = (const uint4*)g_Tt16;
    float acc[4][4][4] = {};
    uint4 ga[2], gb[2];
    int nCh = kPer >> 5;
    LDG16(A4[(m0 + r) * 512 + (kBeg >> 3) + c4],
          A4[(n0 + r) * 512 + (kBeg >> 3) + c4]);
    STS16(0);
    __syncthreads();
    for (int c = 0; c < nCh; c++) {
        int st = c & 1;
        if (c + 1 < nCh) {
            int kc = kBeg + (c + 1) * 32;
            LDG16(A4[(m0 + r) * 512 + (kc >> 3) + c4],
                  A4[(n0 + r) * 512 + (kc >> 3) + c4]);
        }
        MMA16_CHUNK(st);
        if (c + 1 < nCh) STS16(1 - st);
        __syncthreads();
    }
    #pragma unroll
    for (int mi = 0; mi < 4; mi++)
        #pragma unroll
        for (int ni = 0; ni < 4; ni++)
            #pragma unroll
            for (int h = 0; h < 2; h++)
                #pragma unroll
                for (int q = 0; q < 2; q++) {
                    int gi = m0 + wm * 64 + mi * 16 + fr + h * 8;
                    int gj = n0 + wn * 32 + ni * 8 + fc * 2 + q;
                    atomicAdd(&g_TT[gi * TDIM + gj], acc[mi][ni][h * 2 + q]);
                }
}

// ---------------- distill square-reduce ----------------
__global__ void k_sq3() {
    int i = blockIdx.x * 256 + threadIdx.x;
    int n = gridDim.x * 256;
    float s = 0.f;
    for (int j = i; j < HD * HD; j += n) {
        float v = g_GH[j]; s += v * v * (1.f / (128.f * 128.f));
    }
    for (int j = i; j < HD * TDIM; j += n) {
        float v = g_C[j]; s -= 2.f * v * v * (1.f / 128.f);
    }
    for (int j = i; j < TDIM * TDIM; j += n) {
        int r = j / TDIM, c = j % TDIM;
        if (c < r) continue;
        float v = g_TT[j];
        s += (c == r) ? v * v : 2.f * v * v;
    }
    #pragma unroll
    for (int o = 16; o >= 1; o >>= 1) s += __shfl_xor_sync(0xffffffffu, s, o);
    __shared__ float red[8];
    if ((threadIdx.x & 31) == 0) red[threadIdx.x >> 5] = s;
    __syncthreads();
    if (threadIdx.x == 0) {
        float tot = 0.f;
        #pragma unroll
        for (int k = 0; k < 8; k++) tot += red[k];
        atomicAdd(&g_ST, tot / ((float)BSZ * (float)BSZ));
    }
}

// ---------------- contrastive: upper-tri 128-tiles, denominator only --------
__global__ void __launch_bounds__(256) k_cont() {
    __shared__ __align__(16) unsigned As16[2][128][20];
    __shared__ __align__(16) unsigned Bs16[2][128][20];
    __shared__ float sCd[128];
    int t = blockIdx.x, tm = 0;                 // 32x32 tiles, upper = 528
    while (t >= 32 - tm) { t -= 32 - tm; tm++; }
    int i0 = tm * 128, j0 = (tm + t) * 128;
    bool diag = (i0 == j0);
    int tid = threadIdx.x, lane = tid & 31, w = tid >> 5;
    int wm = w & 1, wn = w >> 1;
    int fr = lane >> 2, fc = lane & 3;
    if (tid < 128) sCd[tid] = 0.f;
    const uint4* LN4 = (const uint4*)g_LNh;   // row = 16 uint4 (128 bf16)
    float acc[4][4][4] = {};
    uint4 ga[2], gb[2];
    LDG16(LN4[(i0 + r) * 16 + c4], LN4[(j0 + r) * 16 + c4]);
    STS16(0);
    __syncthreads();
    #pragma unroll
    for (int c = 0; c < 4; c++) {
        int st = c & 1;
        if (c + 1 < 4) {
            LDG16(LN4[(i0 + r) * 16 + (c + 1) * 4 + c4],
                  LN4[(j0 + r) * 16 + (c + 1) * 4 + c4]);
        }
        MMA16_CHUNK(st);
        if (c + 1 < 4) STS16(1 - st);
        __syncthreads();
    }

    // ---- epilogue: exp sums, both orientations ----
    float dR[4][2] = {}, dC[4][2] = {};
    #pragma unroll
    for (int mi = 0; mi < 4; mi++)
        #pragma unroll
        for (int ni = 0; ni < 4; ni++)
            #pragma unroll
            for (int h = 0; h < 2; h++)
                #pragma unroll
                for (int q = 0; q < 2; q++) {
                    int li = wm * 64 + mi * 16 + fr + h * 8;
                    int lj = wn * 32 + ni * 8 + fc * 2 + q;
                    float e = __expf(acc[mi][ni][h * 2 + q] * 5.0f);
                    if (!diag || li != lj) dR[mi][h] += e;
                    if (!diag) dC[ni][q] += e;
                }
    // row reduce over fc lanes (width 4)
    #pragma unroll
    for (int mi = 0; mi < 4; mi++)
        #pragma unroll
        for (int h = 0; h < 2; h++) {
            #pragma unroll
            for (int o = 2; o >= 1; o >>= 1)
                dR[mi][h] += __shfl_down_sync(0xffffffffu, dR[mi][h], o, 4);
            if (fc == 0)
                atomicAdd(&g_denom[i0 + wm * 64 + mi * 16 + fr + h * 8], dR[mi][h]);
        }
    // col reduce over fr lanes (xor 4,8,16)
    if (!diag) {
        #pragma unroll
        for (int ni = 0; ni < 4; ni++)
            #pragma unroll
            for (int q = 0; q < 2; q++) {
                #pragma unroll
                for (int o = 16; o >= 4; o >>= 1)
                    dC[ni][q] += __shfl_xor_sync(0xffffffffu, dC[ni][q], o);
                if (fr == 0)
                    atomicAdd(&sCd[wn * 32 + ni * 8 + fc * 2 + q], dC[ni][q]);
            }
        __syncthreads();
        if (tid < 128) atomicAdd(&g_denom[j0 + tid], sCd[tid]);
    }
}

// ---------------- final combine ----------------
__global__ void k_combine(float* __restrict__ out) {
    int tid = threadIdx.x;               // 256 threads
    float cont = 0.f;
    for (int i = tid; i < BSZ; i += 256)
        cont += logf(g_denom[i]) - g_pos[i] / fmaxf(g_cnt[i], 1.0f);
    #pragma unroll
    for (int o = 16; o >= 1; o >>= 1)
        cont += __shfl_xor_sync(0xffffffffu, cont, o);
    __shared__ float r0[8];
    if ((tid & 31) == 0) r0[tid >> 5] = cont;
    __syncthreads();
    if (tid == 0) {
        float cT = 0.f;
        #pragma unroll
        for (int i = 0; i < 8; i++) cT += r0[i];
        float quant = g_quant / ((float)BSZ * (float)HD);
        out[0] = cT / (float)BSZ + 0.5f * g_ST + 0.01f * quant;
    }
}

// ---------------- launch ----------------
extern "C" void kernel_launch(void* const* d_in, const int* in_sizes, int n_in,
                              void* d_out, int out_size) {
    const float* logits = (const float*)d_in[0];
    const float* hash   = (const float*)d_in[1];
    const float* teach  = (const float*)d_in[2];
    const int*   pmask  = (const int*)d_in[3];
    float* out = (float*)d_out;

    __nv_bfloat16* p_Ht; cudaGetSymbolAddress((void**)&p_Ht, g_Ht16);
    __nv_bfloat16* p_Tt; cudaGetSymbolAddress((void**)&p_Tt, g_Tt16);
    float* p_GH; cudaGetSymbolAddress((void**)&p_GH, g_GH);
    float* p_C;  cudaGetSymbolAddress((void**)&p_C,  g_C);

    k_bits<<<2048, 256>>>(pmask);                                        // 1 (+zero)
    k_norm_logits<<<BSZ, 128>>>(logits);                                 // 2
    k_posbits<<<512, 256>>>();                                           // 3
    k_tnorm<<<128, 256>>>(teach);                                        // 4
    k_transpose_both<<<dim3(28, BSZ / 32), dim3(32, 8)>>>(hash, teach);  // 5
    k_cont<<<528, 256>>>();                                              // 6
    // G_H = H^T H : one 128-tile, split-K 32
    k_gemm16<<<dim3(1, 1, 32), 256>>>(p_Ht, p_Ht, p_GH, HD, 128);
    // C = H^T T : 1x6 128-tiles, split-K 16
    k_gemm16<<<dim3(1, 6, 16), 256>>>(p_Ht, p_Tt, p_C, TDIM, 256);
    // T^T T upper triangle : 21 128-tiles, split-K 16
    k_gemm_tri16<<<dim3(21, 1, 16), 256>>>(256);
    k_sq3<<<512, 256>>>();
    k_combine<<<1, 256>>>(out);
}

// round 11
// speedup vs baseline: 2.3703x; 1.1596x over previous
#include <cuda_runtime.h>
#include <cuda_bf16.h>
#include <math.h>

#define BSZ 4096
#define HD  128
#define TDIM 768

// ---------------- device scratch ----------------
__device__ __align__(16) float g_LN[BSZ * HD];          // normalized logits fp32
__device__ __align__(16) __nv_bfloat16 g_LNh[BSZ * HD]; // normalized logits bf16
__device__ float g_Tn[BSZ];                              // teacher row inv-norms
__device__ __align__(16) __nv_bfloat16 g_Ht16[HD * BSZ];   // hash^T bf16 [128][4096]
__device__ __align__(16) __nv_bfloat16 g_Tt16[TDIM * BSZ]; // norm teacher^T bf16
__device__ float g_GH[HD * HD];
__device__ float g_C [HD * TDIM];
__device__ float g_TT[TDIM * TDIM];
__device__ unsigned g_bm[BSZ * BSZ / 32];  // mask bits [4096][128] u32
__device__ float g_denom[BSZ];
__device__ float g_pos[BSZ];
__device__ float g_cnt[BSZ];
__device__ float g_quant;
__device__ float g_ST;

__device__ __forceinline__ void mma_bf16(float* d, const unsigned* a, const unsigned* b) {
    asm volatile(
        "mma.sync.aligned.m16n8k16.row.col.f32.bf16.bf16.f32 "
        "{%0,%1,%2,%3}, {%4,%5,%6,%7}, {%8,%9}, {%0,%1,%2,%3};"
        : "+f"(d[0]), "+f"(d[1]), "+f"(d[2]), "+f"(d[3])
        : "r"(a[0]), "r"(a[1]), "r"(a[2]), "r"(a[3]), "r"(b[0]), "r"(b[1]));
}

// ---------------- zero: denom + quant (main stream head) ----------------
__global__ void k_zero0() {
    int i = blockIdx.x * 256 + threadIdx.x;
    if (i < BSZ) g_denom[i] = 0.f;
    if (i == 0) g_quant = 0.f;
}

// ---------------- zero: Gram accumulators (s2 head) ----------------
__global__ void k_zero2() {
    int i = blockIdx.x * 256 + threadIdx.x;
    int n = gridDim.x * 256;
    for (int j = i; j < TDIM * TDIM; j += n) g_TT[j] = 0.f;
    for (int j = i; j < HD * TDIM;  j += n) g_C[j]  = 0.f;
    if (i < HD * HD) g_GH[i] = 0.f;
    if (i == 0) g_ST = 0.f;
}

// ---------------- mask -> bitmask (coalesced ballot) ----------------
__global__ void k_bits(const int* __restrict__ pmask) {
    int gi = blockIdx.x * 256 + threadIdx.x;
    int warp = gi >> 5;                  // 16384 warps
    int lane = threadIdx.x & 31;
    long base = (long)warp * 1024;
    unsigned myword = 0;
    #pragma unroll
    for (int s = 0; s < 32; s++) {
        int v = pmask[base + s * 32 + lane];
        unsigned b = __ballot_sync(0xffffffffu, v != 0);
        if (lane == s) myword = b;
    }
    g_bm[base / 32 + lane] = myword;
}

// ---------------- normalize logits + quant partial (fp32 + bf16 out) --------
__global__ void k_norm_logits(const float* __restrict__ x) {
    int row = blockIdx.x;
    int t = threadIdx.x;                 // 128 threads
    float v = x[row * HD + t];
    float ss = v * v;
    float q = fabsf(fabsf(v) - 1.0f);
    #pragma unroll
    for (int o = 16; o >= 1; o >>= 1) {
        ss += __shfl_xor_sync(0xffffffffu, ss, o);
        q  += __shfl_xor_sync(0xffffffffu, q, o);
    }
    __shared__ float sred[4], qred[4];
    __shared__ float sinv;
    int w = t >> 5, l = t & 31;
    if (l == 0) { sred[w] = ss; qred[w] = q; }
    __syncthreads();
    if (t == 0) {
        float tot = sred[0] + sred[1] + sred[2] + sred[3];
        float qt  = qred[0] + qred[1] + qred[2] + qred[3];
        atomicAdd(&g_quant, qt);
        sinv = 1.0f / fmaxf(sqrtf(tot), 1e-12f);
    }
    __syncthreads();
    float nv = v * sinv;
    g_LN[row * HD + t] = nv;
    g_LNh[row * HD + t] = __float2bfloat16(nv);
}

// ---------------- positives: warp-per-row bitmask scan, exact fp32 ----------
__global__ void k_posbits() {
    int warp = (blockIdx.x * blockDim.x + threadIdx.x) >> 5;   // 4096 warps
    int lane = threadIdx.x & 31;
    int row = warp;
    const float4* LN4 = (const float4*)g_LN;   // row stride 32 float4
    float4 a = LN4[row * 32 + lane];
    float ps = 0.f;
    int cnt = 0;
    #pragma unroll
    for (int g = 0; g < 4; g++) {
        unsigned wrd = g_bm[row * 128 + g * 32 + lane];
        unsigned act = __ballot_sync(0xffffffffu, wrd != 0);
        while (act) {
            int src = __ffs(act) - 1; act &= act - 1;
            unsigned w2 = __shfl_sync(0xffffffffu, wrd, src);
            int base = (g * 32 + src) * 32;
            while (w2) {
                int b = __ffs(w2) - 1; w2 &= w2 - 1;
                int j = base + b;
                float4 bb = LN4[j * 32 + lane];
                float d = a.x * bb.x + a.y * bb.y + a.z * bb.z + a.w * bb.w;
                #pragma unroll
                for (int o = 16; o >= 1; o >>= 1)
                    d += __shfl_xor_sync(0xffffffffu, d, o);
                ps += d; cnt++;
            }
        }
    }
    if (lane == 0) { g_pos[row] = ps * 5.0f; g_cnt[row] = (float)cnt; }
}

// ---------------- teacher row inv norms (warp-per-row, 4096 warps) ----------
__global__ void k_tnorm(const float* __restrict__ x) {
    int row = (blockIdx.x * blockDim.x + threadIdx.x) >> 5;   // 4096 warps
    int lane = threadIdx.x & 31;
    const float4* x4 = (const float4*)(x + row * TDIM);       // 192 float4
    float ss = 0.f;
    #pragma unroll
    for (int i = 0; i < 6; i++) {
        float4 v = x4[lane + i * 32];
        ss += v.x * v.x + v.y * v.y + v.z * v.z + v.w * v.w;
    }
    #pragma unroll
    for (int o = 16; o >= 1; o >>= 1) ss += __shfl_xor_sync(0xffffffffu, ss, o);
    if (lane == 0) g_Tn[row] = 1.0f / fmaxf(sqrtf(ss), 1e-12f);
}

// ---------------- fused transposes -> bf16 (hash + scaled teacher) ----------
__global__ void k_transpose_both(const float* __restrict__ hash,
                                 const float* __restrict__ teach) {
    __shared__ float t[32][33];
    int x = threadIdx.x, y = threadIdx.y;   // block (32, 8)
    int r0 = blockIdx.y * 32;
    if (blockIdx.x < 4) {
        int c0 = blockIdx.x * 32;
        #pragma unroll
        for (int i = 0; i < 32; i += 8) t[y + i][x] = hash[(r0 + y + i) * HD + c0 + x];
        __syncthreads();
        #pragma unroll
        for (int i = 0; i < 32; i += 8)
            g_Ht16[(c0 + y + i) * BSZ + r0 + x] = __float2bfloat16(t[x][y + i]);
    } else {
        int c0 = (blockIdx.x - 4) * 32;
        #pragma unroll
        for (int i = 0; i < 32; i += 8)
            t[y + i][x] = teach[(r0 + y + i) * TDIM + c0 + x] * g_Tn[r0 + y + i];
        __syncthreads();
        #pragma unroll
        for (int i = 0; i < 32; i += 8)
            g_Tt16[(c0 + y + i) * BSZ + r0 + x] = __float2bfloat16(t[x][y + i]);
    }
}

// ======== 128x128 double-buffered bf16 mma core, K-chunk 32 ========
// smem u32 [2][128][20]; 8 warps = 2(wm) x 4(wn); warp tile 64x32; 4(mi)x4(ni)

#define LDG16(Aexpr, Bexpr)                                                 \
    do {                                                                    \
        _Pragma("unroll")                                                   \
        for (int s = 0; s < 2; s++) {                                       \
            int idx = tid + s * 256;                                        \
            int r = idx >> 2, c4 = idx & 3;                                 \
            ga[s] = (Aexpr); gb[s] = (Bexpr);                               \
        }                                                                   \
    } while (0)

#define STS16(st)                                                           \
    do {                                                                    \
        _Pragma("unroll")                                                   \
        for (int s = 0; s < 2; s++) {                                       \
            int idx = tid + s * 256;                                        \
            int r = idx >> 2, c4 = idx & 3;                                 \
            *(uint4*)&As16[st][r][c4 * 4] = ga[s];                          \
            *(uint4*)&Bs16[st][r][c4 * 4] = gb[s];                          \
        }                                                                   \
    } while (0)

#define MMA16_CHUNK(st)                                                     \
    do {                                                                    \
        _Pragma("unroll")                                                   \
        for (int kk = 0; kk < 2; kk++) {                                    \
            int kb = kk * 8;                                                \
            unsigned af[4][4], bf[4][2];                                    \
            _Pragma("unroll")                                               \
            for (int mi = 0; mi < 4; mi++) {                                \
                int rr = wm * 64 + mi * 16 + fr;                            \
                af[mi][0] = As16[st][rr][kb + fc];                          \
                af[mi][1] = As16[st][rr + 8][kb + fc];                      \
                af[mi][2] = As16[st][rr][kb + fc + 4];                      \
                af[mi][3] = As16[st][rr + 8][kb + fc + 4];                  \
            }                                                               \
            _Pragma("unroll")                                               \
            for (int ni = 0; ni < 4; ni++) {                                \
                int rn = wn * 32 + ni * 8 + fr;                             \
                bf[ni][0] = Bs16[st][rn][kb + fc];                          \
                bf[ni][1] = Bs16[st][rn][kb + fc + 4];                      \
            }                                                               \
            _Pragma("unroll")                                               \
            for (int mi = 0; mi < 4; mi++)                                  \
                _Pragma("unroll")                                           \
                for (int ni = 0; ni < 4; ni++)                              \
                    mma_bf16(acc[mi][ni], af[mi], bf[ni]);                  \
        }                                                                   \
    } while (0)

// ---------------- generic bf16 A*B^T GEMM (k-contig [rows][4096]) -----------
__global__ void __launch_bounds__(256) k_gemm16(const __nv_bfloat16* __restrict__ A,
                                                const __nv_bfloat16* __restrict__ Bm,
                                                float* __restrict__ out, int ldo,
                                                int kPer) {
    __shared__ __align__(16) unsigned As16[2][128][20];
    __shared__ __align__(16) unsigned Bs16[2][128][20];
    int m0 = blockIdx.x * 128, n0 = blockIdx.y * 128;
    int kBeg = blockIdx.z * kPer;
    int tid = threadIdx.x, lane = tid & 31, w = tid >> 5;
    int wm = w & 1, wn = w >> 1;
    int fr = lane >> 2, fc = lane & 3;
    const uint4* A4 = (const uint4*)A;    // row = 512 uint4
    const uint4* B4 = (const uint4*)Bm;
    float acc[4][4][4] = {};
    uint4 ga[2], gb[2];
    int nCh = kPer >> 5;
    LDG16(A4[(m0 + r) * 512 + (kBeg >> 3) + c4],
          B4[(n0 + r) * 512 + (kBeg >> 3) + c4]);
    STS16(0);
    __syncthreads();
    for (int c = 0; c < nCh; c++) {
        int st = c & 1;
        if (c + 1 < nCh) {
            int kc = kBeg + (c + 1) * 32;
            LDG16(A4[(m0 + r) * 512 + (kc >> 3) + c4],
                  B4[(n0 + r) * 512 + (kc >> 3) + c4]);
        }
        MMA16_CHUNK(st);
        if (c + 1 < nCh) STS16(1 - st);
        __syncthreads();
    }
    #pragma unroll
    for (int mi = 0; mi < 4; mi++)
        #pragma unroll
        for (int ni = 0; ni < 4; ni++)
            #pragma unroll
            for (int h = 0; h < 2; h++)
                #pragma unroll
                for (int q = 0; q < 2; q++) {
                    int gi = m0 + wm * 64 + mi * 16 + fr + h * 8;
                    int gj = n0 + wn * 32 + ni * 8 + fc * 2 + q;
                    atomicAdd(&out[gi * ldo + gj], acc[mi][ni][h * 2 + q]);
                }
}

// ---------------- T^T T upper-triangle 128-tiles (bf16) ----------------
__global__ void __launch_bounds__(256) k_gemm_tri16(int kPer) {
    __shared__ __align__(16) unsigned As16[2][128][20];
    __shared__ __align__(16) unsigned Bs16[2][128][20];
    int t = blockIdx.x, tm = 0;                 // 6x6 tiles, upper = 21
    while (t >= 6 - tm) { t -= 6 - tm; tm++; }
    int m0 = tm * 128, n0 = (tm + t) * 128;
    int kBeg = blockIdx.z * kPer;
    int tid = threadIdx.x, lane = tid & 31, w = tid >> 5;
    int wm = w & 1, wn = w >> 1;
    int fr = lane >> 2, fc = lane & 3;
    const uint4* A4 = (const uint4*)g_Tt16;
    float acc[4][4][4] = {};
    uint4 ga[2], gb[2];
    int nCh = kPer >> 5;
    LDG16(A4[(m0 + r) * 512 + (kBeg >> 3) + c4],
          A4[(n0 + r) * 512 + (kBeg >> 3) + c4]);
    STS16(0);
    __syncthreads();
    for (int c = 0; c < nCh; c++) {
        int st = c & 1;
        if (c + 1 < nCh) {
            int kc = kBeg + (c + 1) * 32;
            LDG16(A4[(m0 + r) * 512 + (kc >> 3) + c4],
                  A4[(n0 + r) * 512 + (kc >> 3) + c4]);
        }
        MMA16_CHUNK(st);
        if (c + 1 < nCh) STS16(1 - st);
        __syncthreads();
    }
    #pragma unroll
    for (int mi = 0; mi < 4; mi++)
        #pragma unroll
        for (int ni = 0; ni < 4; ni++)
            #pragma unroll
            for (int h = 0; h < 2; h++)
                #pragma unroll
                for (int q = 0; q < 2; q++) {
                    int gi = m0 + wm * 64 + mi * 16 + fr + h * 8;
                    int gj = n0 + wn * 32 + ni * 8 + fc * 2 + q;
                    atomicAdd(&g_TT[gi * TDIM + gj], acc[mi][ni][h * 2 + q]);
                }
}

// ---------------- distill square-reduce ----------------
__global__ void k_sq3() {
    int i = blockIdx.x * 256 + threadIdx.x;
    int n = gridDim.x * 256;
    float s = 0.f;
    for (int j = i; j < HD * HD; j += n) {
        float v = g_GH[j]; s += v * v * (1.f / (128.f * 128.f));
    }
    for (int j = i; j < HD * TDIM; j += n) {
        float v = g_C[j]; s -= 2.f * v * v * (1.f / 128.f);
    }
    for (int j = i; j < TDIM * TDIM; j += n) {
        int r = j / TDIM, c = j % TDIM;
        if (c < r) continue;
        float v = g_TT[j];
        s += (c == r) ? v * v : 2.f * v * v;
    }
    #pragma unroll
    for (int o = 16; o >= 1; o >>= 1) s += __shfl_xor_sync(0xffffffffu, s, o);
    __shared__ float red[8];
    if ((threadIdx.x & 31) == 0) red[threadIdx.x >> 5] = s;
    __syncthreads();
    if (threadIdx.x == 0) {
        float tot = 0.f;
        #pragma unroll
        for (int k = 0; k < 8; k++) tot += red[k];
        atomicAdd(&g_ST, tot / ((float)BSZ * (float)BSZ));
    }
}

// ---------------- contrastive: upper-tri 128-tiles, denominator only --------
__global__ void __launch_bounds__(256) k_cont() {
    __shared__ __align__(16) unsigned As16[2][128][20];
    __shared__ __align__(16) unsigned Bs16[2][128][20];
    __shared__ float sCd[128];
    int t = blockIdx.x, tm = 0;                 // 32x32 tiles, upper = 528
    while (t >= 32 - tm) { t -= 32 - tm; tm++; }
    int i0 = tm * 128, j0 = (tm + t) * 128;
    bool diag = (i0 == j0);
    int tid = threadIdx.x, lane = tid & 31, w = tid >> 5;
    int wm = w & 1, wn = w >> 1;
    int fr = lane >> 2, fc = lane & 3;
    if (tid < 128) sCd[tid] = 0.f;
    const uint4* LN4 = (const uint4*)g_LNh;   // row = 16 uint4 (128 bf16)
    float acc[4][4][4] = {};
    uint4 ga[2], gb[2];
    LDG16(LN4[(i0 + r) * 16 + c4], LN4[(j0 + r) * 16 + c4]);
    STS16(0);
    __syncthreads();
    #pragma unroll
    for (int c = 0; c < 4; c++) {
        int st = c & 1;
        if (c + 1 < 4) {
            LDG16(LN4[(i0 + r) * 16 + (c + 1) * 4 + c4],
                  LN4[(j0 + r) * 16 + (c + 1) * 4 + c4]);
        }
        MMA16_CHUNK(st);
        if (c + 1 < 4) STS16(1 - st);
        __syncthreads();
    }

    // ---- epilogue: exp sums, both orientations ----
    float dR[4][2] = {}, dC[4][2] = {};
    #pragma unroll
    for (int mi = 0; mi < 4; mi++)
        #pragma unroll
        for (int ni = 0; ni < 4; ni++)
            #pragma unroll
            for (int h = 0; h < 2; h++)
                #pragma unroll
                for (int q = 0; q < 2; q++) {
                    int li = wm * 64 + mi * 16 + fr + h * 8;
                    int lj = wn * 32 + ni * 8 + fc * 2 + q;
                    float e = __expf(acc[mi][ni][h * 2 + q] * 5.0f);
                    if (!diag || li != lj) dR[mi][h] += e;
                    if (!diag) dC[ni][q] += e;
                }
    #pragma unroll
    for (int mi = 0; mi < 4; mi++)
        #pragma unroll
        for (int h = 0; h < 2; h++) {
            #pragma unroll
            for (int o = 2; o >= 1; o >>= 1)
                dR[mi][h] += __shfl_down_sync(0xffffffffu, dR[mi][h], o, 4);
            if (fc == 0)
                atomicAdd(&g_denom[i0 + wm * 64 + mi * 16 + fr + h * 8], dR[mi][h]);
        }
    if (!diag) {
        #pragma unroll
        for (int ni = 0; ni < 4; ni++)
            #pragma unroll
            for (int q = 0; q < 2; q++) {
                #pragma unroll
                for (int o = 16; o >= 4; o >>= 1)
                    dC[ni][q] += __shfl_xor_sync(0xffffffffu, dC[ni][q], o);
                if (fr == 0)
                    atomicAdd(&sCd[wn * 32 + ni * 8 + fc * 2 + q], dC[ni][q]);
            }
        __syncthreads();
        if (tid < 128) atomicAdd(&g_denom[j0 + tid], sCd[tid]);
    }
}

// ---------------- final combine ----------------
__global__ void k_combine(float* __restrict__ out) {
    int tid = threadIdx.x;               // 256 threads
    float cont = 0.f;
    for (int i = tid; i < BSZ; i += 256)
        cont += logf(g_denom[i]) - g_pos[i] / fmaxf(g_cnt[i], 1.0f);
    #pragma unroll
    for (int o = 16; o >= 1; o >>= 1)
        cont += __shfl_xor_sync(0xffffffffu, cont, o);
    __shared__ float r0[8];
    if ((tid & 31) == 0) r0[tid >> 5] = cont;
    __syncthreads();
    if (tid == 0) {
        float cT = 0.f;
        #pragma unroll
        for (int i = 0; i < 8; i++) cT += r0[i];
        float quant = g_quant / ((float)BSZ * (float)HD);
        out[0] = cT / (float)BSZ + 0.5f * g_ST + 0.01f * quant;
    }
}

// ---------------- launch: fork-join across 3 streams ----------------
extern "C" void kernel_launch(void* const* d_in, const int* in_sizes, int n_in,
                              void* d_out, int out_size) {
    const float* logits = (const float*)d_in[0];
    const float* hash   = (const float*)d_in[1];
    const float* teach  = (const float*)d_in[2];
    const int*   pmask  = (const int*)d_in[3];
    float* out = (float*)d_out;

    __nv_bfloat16* p_Ht; cudaGetSymbolAddress((void**)&p_Ht, g_Ht16);
    __nv_bfloat16* p_Tt; cudaGetSymbolAddress((void**)&p_Tt, g_Tt16);
    float* p_GH; cudaGetSymbolAddress((void**)&p_GH, g_GH);
    float* p_C;  cudaGetSymbolAddress((void**)&p_C,  g_C);

    static cudaStream_t s1 = 0, s2 = 0;
    static cudaEvent_t evStart = 0, evA = 0, ev1 = 0, ev2 = 0;
    if (s1 == 0) {
        cudaStreamCreateWithFlags(&s1, cudaStreamNonBlocking);
        cudaStreamCreateWithFlags(&s2, cudaStreamNonBlocking);
        cudaEventCreateWithFlags(&evStart, cudaEventDisableTiming);
        cudaEventCreateWithFlags(&evA, cudaEventDisableTiming);
        cudaEventCreateWithFlags(&ev1, cudaEventDisableTiming);
        cudaEventCreateWithFlags(&ev2, cudaEventDisableTiming);
    }
    cudaStream_t s0 = 0;   // legacy default (capture) stream

    cudaEventRecord(evStart, s0);
    cudaStreamWaitEvent(s1, evStart, 0);
    cudaStreamWaitEvent(s2, evStart, 0);

    // ---- main: logits chain + k_cont (tensor-bound) ----
    k_zero0<<<16, 256, 0, s0>>>();
    k_norm_logits<<<BSZ, 128, 0, s0>>>(logits);
    cudaEventRecord(evA, s0);
    k_cont<<<528, 256, 0, s0>>>();

    // ---- s1: mask bits (DRAM-bound) + exact positives ----
    k_bits<<<2048, 256, 0, s1>>>(pmask);
    cudaStreamWaitEvent(s1, evA, 0);
    k_posbits<<<512, 256, 0, s1>>>();
    cudaEventRecord(ev1, s1);

    // ---- s2: distill chain ----
    k_zero2<<<512, 256, 0, s2>>>();
    k_tnorm<<<512, 256, 0, s2>>>(teach);
    k_transpose_both<<<dim3(28, BSZ / 32), dim3(32, 8), 0, s2>>>(hash, teach);
    k_gemm16<<<dim3(1, 1, 32), 256, 0, s2>>>(p_Ht, p_Ht, p_GH, HD, 128);
    k_gemm16<<<dim3(1, 6, 16), 256, 0, s2>>>(p_Ht, p_Tt, p_C, TDIM, 256);
    k_gemm_tri16<<<dim3(21, 1, 16), 256, 0, s2>>>(256);
    k_sq3<<<512, 256, 0, s2>>>();
    cudaEventRecord(ev2, s2);

    // ---- join ----
    cudaStreamWaitEvent(s0, ev1, 0);
    cudaStreamWaitEvent(s0, ev2, 0);
    k_combine<<<1, 256, 0, s0>>>(out);
}